// round 1
// baseline (speedup 1.0000x reference)
#include <cuda_runtime.h>
#include <math.h>

#define NN   100000
#define EE   1600000
#define FIN  20
#define HH   128
#define EPSV 1e-5f

// ---------------- scratch (static device arrays; no allocation) ----------------
__device__ __align__(16) float g_agg[NN * HH];
__device__ __align__(16) float g_pre[NN * HH];
__device__ __align__(16) float g_h[NN * HH];
__device__ int   g_deg[NN];        // degree, then reused as fill cursor
__device__ int   g_off[NN + 1];
__device__ int   g_csr[EE];
__device__ int   g_bsum[128];
__device__ float g_stats[2 * HH];  // per-channel sum, sumsq
__device__ float g_norm[2 * HH];   // per-channel scale, shifted bias

typedef unsigned long long ull;

__device__ __forceinline__ ull pk2(float lo, float hi) {
    ull r; asm("mov.b64 %0, {%1,%2};" : "=l"(r) : "f"(lo), "f"(hi)); return r;
}
__device__ __forceinline__ void upk2(ull v, float& lo, float& hi) {
    asm("mov.b64 {%0,%1}, %2;" : "=f"(lo), "=f"(hi) : "l"(v));
}
__device__ __forceinline__ void fma2(ull& d, ull a, ull b) {
    asm("fma.rn.f32x2 %0, %1, %2, %0;" : "+l"(d) : "l"(a), "l"(b));
}
__device__ __forceinline__ float gelu_f(float x) {
    return 0.5f * x * (1.0f + erff(x * 0.70710678118654752f));
}

// ---------------- CSR build ----------------
__global__ void k_zero_deg() {
    int i = blockIdx.x * blockDim.x + threadIdx.x;
    if (i < NN) g_deg[i] = 0;
}
__global__ void k_hist(const int* __restrict__ ei) {
    int e = blockIdx.x * blockDim.x + threadIdx.x;
    if (e < EE) atomicAdd(&g_deg[ei[EE + e]], 1);
}
__global__ void k_scan1() {
    __shared__ int s[1024];
    int t = threadIdx.x;
    int i = blockIdx.x * 1024 + t;
    int v = (i < NN) ? g_deg[i] : 0;
    s[t] = v;
    __syncthreads();
#pragma unroll
    for (int d = 1; d < 1024; d <<= 1) {
        int x = (t >= d) ? s[t - d] : 0;
        __syncthreads();
        s[t] += x;
        __syncthreads();
    }
    if (i < NN) g_off[i + 1] = s[t];   // local inclusive scan
    if (t == 1023) g_bsum[blockIdx.x] = s[1023];
}
__global__ void k_scan2(int nb) {
    if (threadIdx.x == 0) {
        int run = 0;
        for (int b = 0; b < nb; b++) { int v = g_bsum[b]; g_bsum[b] = run; run += v; }
    }
}
__global__ void k_scan3() {
    int i = blockIdx.x * blockDim.x + threadIdx.x;
    if (i < NN) {
        int tot = g_off[i + 1] + g_bsum[i >> 10];
        g_off[i + 1] = tot;
        int d = g_deg[i];
        g_deg[i] = tot - d;           // cursor = exclusive offset
        if (i == 0) g_off[0] = 0;
    }
}
__global__ void k_fill(const int* __restrict__ ei) {
    int e = blockIdx.x * blockDim.x + threadIdx.x;
    if (e < EE) {
        int d = ei[EE + e];
        int pos = atomicAdd(&g_deg[d], 1);
        g_csr[pos] = ei[e];
    }
}

// ---------------- aggregation ----------------
__global__ void k_agg20(const float* __restrict__ x) {
    int w = (blockIdx.x * blockDim.x + threadIdx.x) >> 5;
    int lane = threadIdx.x & 31;
    if (w >= NN) return;
    int off = g_off[w], end = g_off[w + 1];
    float acc = 0.f;
    for (int j = off; j < end; j += 32) {
        int idx = (j + lane < end) ? g_csr[j + lane] : 0;
        int cnt = min(32, end - j);
        for (int t = 0; t < cnt; t++) {
            int s = __shfl_sync(0xffffffffu, idx, t);
            if (lane < FIN) acc += x[s * FIN + lane];
        }
    }
    if (lane < FIN) {
        int deg = end - off;
        g_agg[w * FIN + lane] = acc * (deg > 0 ? 1.f / (float)deg : 0.f);
    }
}

__global__ void k_agg128() {
    int w = (blockIdx.x * blockDim.x + threadIdx.x) >> 5;
    int lane = threadIdx.x & 31;
    if (w >= NN) return;
    int off = g_off[w], end = g_off[w + 1];
    const float4* h4 = (const float4*)g_h;
    float4 acc = make_float4(0.f, 0.f, 0.f, 0.f);
    for (int j = off; j < end; j += 32) {
        int idx = (j + lane < end) ? g_csr[j + lane] : 0;
        int cnt = min(32, end - j);
        for (int t = 0; t < cnt; t++) {
            int s = __shfl_sync(0xffffffffu, idx, t);
            float4 v = h4[s * 32 + lane];
            acc.x += v.x; acc.y += v.y; acc.z += v.z; acc.w += v.w;
        }
    }
    int deg = end - off;
    float inv = (deg > 0) ? 1.f / (float)deg : 0.f;
    acc.x *= inv; acc.y *= inv; acc.z *= inv; acc.w *= inv;
    ((float4*)g_agg)[w * 32 + lane] = acc;
}

// ---------------- layer-0 GEMM (K=20) ----------------
__global__ __launch_bounds__(256) void k_gemm0(
    const float* __restrict__ x, const float* __restrict__ Wl,
    const float* __restrict__ bl, const float* __restrict__ Wr)
{
    __shared__ float Wls[FIN][HH], Wrs[FIN][HH], bls[HH];
    __shared__ float as_[16][FIN], xs_[16][FIN];
    int tid = threadIdx.x;
    for (int e = tid; e < HH * FIN; e += 256) {
        int o = e / FIN, k = e % FIN;
        Wls[k][o] = Wl[e];
        Wrs[k][o] = Wr[e];
    }
    if (tid < HH) bls[tid] = bl[tid];
    int n0 = blockIdx.x * 16;
    for (int e = tid; e < 16 * FIN; e += 256) {
        int i = e / FIN, k = e % FIN;
        int n = n0 + i;
        float a = 0.f, xx = 0.f;
        if (n < NN) { a = g_agg[n * FIN + k]; xx = x[n * FIN + k]; }
        as_[i][k] = a; xs_[i][k] = xx;
    }
    __syncthreads();
    int i = tid >> 4, oc = tid & 15;
    float acc[8];
#pragma unroll
    for (int j = 0; j < 8; j++) acc[j] = bls[oc * 8 + j];
#pragma unroll
    for (int k = 0; k < FIN; k++) {
        float a = as_[i][k], xv = xs_[i][k];
#pragma unroll
        for (int j = 0; j < 8; j++)
            acc[j] += a * Wls[k][oc * 8 + j] + xv * Wrs[k][oc * 8 + j];
    }
    int n = n0 + i;
    if (n < NN) {
#pragma unroll
        for (int j = 0; j < 8; j++) g_pre[n * HH + oc * 8 + j] = acc[j];
    }
}

// ---------------- 128x128 dual GEMM: pre = agg@Wl^T + h@Wr^T + bl ----------------
__global__ __launch_bounds__(256) void k_gemm128(
    const float* __restrict__ W0, const float* __restrict__ W1,
    const float* __restrict__ bias)
{
    __shared__ __align__(16) float As[16][128];
    __shared__ __align__(16) float Bs[16][128];
    int tid = threadIdx.x;
    int m0 = blockIdx.x * 128;
    int tn = tid & 15, tm = tid >> 4;
    ull acc[8][4];
#pragma unroll
    for (int r = 0; r < 8; r++)
#pragma unroll
        for (int c = 0; c < 4; c++) acc[r][c] = 0ull;

#pragma unroll 1
    for (int phase = 0; phase < 2; phase++) {
        const float4* A4 = (const float4*)(phase ? g_h : g_agg);
        const float4* W4 = (const float4*)(phase ? W1 : W0);
#pragma unroll 1
        for (int kt = 0; kt < 8; kt++) {
            int kb4 = kt * 4;
            __syncthreads();
#pragma unroll
            for (int q = 0; q < 2; q++) {
                int id = tid + q * 256;
                int m = id >> 2, kc = id & 3;
                int row = m0 + m;
                float4 v = make_float4(0.f, 0.f, 0.f, 0.f);
                if (row < NN) v = A4[row * 32 + kb4 + kc];
                As[kc * 4 + 0][m] = v.x; As[kc * 4 + 1][m] = v.y;
                As[kc * 4 + 2][m] = v.z; As[kc * 4 + 3][m] = v.w;
                float4 w = W4[m * 32 + kb4 + kc];
                Bs[kc * 4 + 0][m] = w.x; Bs[kc * 4 + 1][m] = w.y;
                Bs[kc * 4 + 2][m] = w.z; Bs[kc * 4 + 3][m] = w.w;
            }
            __syncthreads();
#pragma unroll
            for (int k = 0; k < 16; k++) {
                float4 a0 = *(const float4*)&As[k][tm * 8];
                float4 a1 = *(const float4*)&As[k][tm * 8 + 4];
                const ull* brow = (const ull*)&Bs[k][tn * 8];
                ull b0 = brow[0], b1 = brow[1], b2 = brow[2], b3 = brow[3];
                float ar[8] = {a0.x, a0.y, a0.z, a0.w, a1.x, a1.y, a1.z, a1.w};
#pragma unroll
                for (int r = 0; r < 8; r++) {
                    ull a2 = pk2(ar[r], ar[r]);
                    fma2(acc[r][0], a2, b0);
                    fma2(acc[r][1], a2, b1);
                    fma2(acc[r][2], a2, b2);
                    fma2(acc[r][3], a2, b3);
                }
            }
        }
    }
    int colbase = tn * 8;
#pragma unroll
    for (int r = 0; r < 8; r++) {
        int row = m0 + tm * 8 + r;
        if (row < NN) {
            float* o = g_pre + row * HH + colbase;
#pragma unroll
            for (int c = 0; c < 4; c++) {
                float lo, hi;
                upk2(acc[r][c], lo, hi);
                o[2 * c]     = lo + bias[colbase + 2 * c];
                o[2 * c + 1] = hi + bias[colbase + 2 * c + 1];
            }
        }
    }
}

// ---------------- GraphNorm stats + apply + GELU ----------------
__global__ void k_zstats() {
    int t = threadIdx.x;
    if (t < 2 * HH) g_stats[t] = 0.f;
}
__global__ void k_stats() {
    int c = threadIdx.x;  // 128 threads
    float s = 0.f, s2 = 0.f;
    for (int r = blockIdx.x; r < NN; r += gridDim.x) {
        float v = g_pre[r * HH + c];
        s += v; s2 += v * v;
    }
    atomicAdd(&g_stats[c], s);
    atomicAdd(&g_stats[HH + c], s2);
}
__global__ void k_finish(const float* __restrict__ gw, const float* __restrict__ gb,
                         const float* __restrict__ ga) {
    int c = threadIdx.x;  // 128 threads
    float invn = 1.f / (float)NN;
    float m  = g_stats[c] * invn;
    float e2 = g_stats[HH + c] * invn;
    float a = ga[c];
    float var = e2 - m * m * (2.f * a - a * a);
    var = fmaxf(var, 0.f);
    float rstd = rsqrtf(var + EPSV);
    float scale = gw[c] * rstd;
    g_norm[c] = scale;
    g_norm[HH + c] = gb[c] - a * m * scale;
}
__global__ void k_normgelu() {
    int i = blockIdx.x * blockDim.x + threadIdx.x;  // float4 index
    if (i >= NN * 32) return;
    int c4 = (i & 31) * 4;
    float4 v = ((const float4*)g_pre)[i];
    float4 r;
    r.x = gelu_f(v.x * g_norm[c4 + 0] + g_norm[HH + c4 + 0]);
    r.y = gelu_f(v.y * g_norm[c4 + 1] + g_norm[HH + c4 + 1]);
    r.z = gelu_f(v.z * g_norm[c4 + 2] + g_norm[HH + c4 + 2]);
    r.w = gelu_f(v.w * g_norm[c4 + 3] + g_norm[HH + c4 + 3]);
    ((float4*)g_h)[i] = r;
}

// ---------------- fused MLP head 128->64->32->1 ----------------
__global__ __launch_bounds__(128) void k_mlp(
    const float* __restrict__ hW1, const float* __restrict__ hb1,
    const float* __restrict__ hW2, const float* __restrict__ hb2,
    const float* __restrict__ hW3, const float* __restrict__ hb3,
    float* __restrict__ out)
{
    extern __shared__ float sm[];
    float* W1t = sm;                 // [128][64]  (k-major)
    float* W2t = W1t + 128 * 64;     // [64][32]
    float* w3  = W2t + 64 * 32;      // [32]
    float* b1  = w3 + 32;            // [64]
    float* b2  = b1 + 64;            // [32]
    float* hs  = b2 + 32;            // [128][129] k-major, padded

    int tid = threadIdx.x;
    for (int e = tid; e < 8192; e += 128) { int o = e >> 7, k = e & 127; W1t[k * 64 + o] = hW1[e]; }
    for (int e = tid; e < 2048; e += 128) { int o = e >> 6, k = e & 63;  W2t[k * 32 + o] = hW2[e]; }
    if (tid < 32) w3[tid] = hW3[tid];
    if (tid < 64) b1[tid] = hb1[tid];
    if (tid < 32) b2[tid] = hb2[tid];

    int n0 = blockIdx.x * 128;
    const float4* h4 = (const float4*)g_h;
    for (int e = tid; e < 128 * 32; e += 128) {
        int r = e >> 5, cc = e & 31;
        int n = n0 + r;
        float4 v = make_float4(0.f, 0.f, 0.f, 0.f);
        if (n < NN) v = h4[n * 32 + cc];
        int kb = cc * 4;
        hs[(kb + 0) * 129 + r] = v.x;
        hs[(kb + 1) * 129 + r] = v.y;
        hs[(kb + 2) * 129 + r] = v.z;
        hs[(kb + 3) * 129 + r] = v.w;
    }
    __syncthreads();

    int n = n0 + tid;
    if (n >= NN) return;

    ull acc1[32];
#pragma unroll
    for (int i = 0; i < 32; i++) acc1[i] = pk2(b1[2 * i], b1[2 * i + 1]);
    for (int k = 0; k < 128; k++) {
        float hv = hs[k * 129 + tid];
        ull a2 = pk2(hv, hv);
        const ull* wr = (const ull*)(W1t + k * 64);
#pragma unroll
        for (int i = 0; i < 32; i++) fma2(acc1[i], a2, wr[i]);
    }
    float y1[64];
#pragma unroll
    for (int i = 0; i < 32; i++) {
        float lo, hi;
        upk2(acc1[i], lo, hi);
        y1[2 * i] = gelu_f(lo);
        y1[2 * i + 1] = gelu_f(hi);
    }
    ull acc2[16];
#pragma unroll
    for (int i = 0; i < 16; i++) acc2[i] = pk2(b2[2 * i], b2[2 * i + 1]);
#pragma unroll 4
    for (int k = 0; k < 64; k++) {
        ull a2 = pk2(y1[k], y1[k]);
        const ull* wr = (const ull*)(W2t + k * 32);
#pragma unroll
        for (int i = 0; i < 16; i++) fma2(acc2[i], a2, wr[i]);
    }
    float s = 0.f;
#pragma unroll
    for (int i = 0; i < 16; i++) {
        float lo, hi;
        upk2(acc2[i], lo, hi);
        s += gelu_f(lo) * w3[2 * i] + gelu_f(hi) * w3[2 * i + 1];
    }
    s += hb3[0];
    out[n] = 1.f / (1.f + expf(-s));
}

// ---------------- launch ----------------
extern "C" void kernel_launch(void* const* d_in, const int* in_sizes, int n_in,
                              void* d_out, int out_size)
{
    const float* x   = (const float*)d_in[0];
    const int*   ei  = (const int*)d_in[1];
    const float* Wl[3] = {(const float*)d_in[2],  (const float*)d_in[8],  (const float*)d_in[14]};
    const float* bl[3] = {(const float*)d_in[3],  (const float*)d_in[9],  (const float*)d_in[15]};
    const float* Wr[3] = {(const float*)d_in[4],  (const float*)d_in[10], (const float*)d_in[16]};
    const float* gw[3] = {(const float*)d_in[5],  (const float*)d_in[11], (const float*)d_in[17]};
    const float* gb[3] = {(const float*)d_in[6],  (const float*)d_in[12], (const float*)d_in[18]};
    const float* ga[3] = {(const float*)d_in[7],  (const float*)d_in[13], (const float*)d_in[19]};
    const float* hW1 = (const float*)d_in[20];
    const float* hb1 = (const float*)d_in[21];
    const float* hW2 = (const float*)d_in[22];
    const float* hb2 = (const float*)d_in[23];
    const float* hW3 = (const float*)d_in[24];
    const float* hb3 = (const float*)d_in[25];
    float* out = (float*)d_out;

    const int SCAN_BLOCKS = (NN + 1023) / 1024;      // 98
    const int MLP_SMEM = (8192 + 2048 + 32 + 64 + 32 + 128 * 129) * 4;
    cudaFuncSetAttribute(k_mlp, cudaFuncAttributeMaxDynamicSharedMemorySize, MLP_SMEM);

    // CSR build
    k_zero_deg<<<(NN + 255) / 256, 256>>>();
    k_hist<<<(EE + 255) / 256, 256>>>(ei);
    k_scan1<<<SCAN_BLOCKS, 1024>>>();
    k_scan2<<<1, 32>>>(SCAN_BLOCKS);
    k_scan3<<<(NN + 255) / 256, 256>>>();
    k_fill<<<(EE + 255) / 256, 256>>>(ei);

    // layer 0 (K=20)
    k_agg20<<<(NN * 32 + 255) / 256, 256>>>(x);
    k_gemm0<<<(NN + 15) / 16, 256>>>(x, Wl[0], bl[0], Wr[0]);
    k_zstats<<<1, 256>>>();
    k_stats<<<512, 128>>>();
    k_finish<<<1, 128>>>(gw[0], gb[0], ga[0]);
    k_normgelu<<<(NN * 32 + 255) / 256, 256>>>();

    // layers 1, 2 (K=128)
    for (int L = 1; L <= 2; L++) {
        k_agg128<<<(NN * 32 + 255) / 256, 256>>>();
        k_gemm128<<<(NN + 127) / 128, 256>>>(Wl[L], Wr[L], bl[L]);
        k_zstats<<<1, 256>>>();
        k_stats<<<512, 128>>>();
        k_finish<<<1, 128>>>(gw[L], gb[L], ga[L]);
        k_normgelu<<<(NN * 32 + 255) / 256, 256>>>();
    }

    // MLP head
    k_mlp<<<(NN + 127) / 128, 128, MLP_SMEM>>>(hW1, hb1, hW2, hb2, hW3, hb3, out);
}

// round 2
// speedup vs baseline: 1.2037x; 1.2037x over previous
#include <cuda_runtime.h>
#include <math.h>

#define NN   100000
#define EE   1600000
#define FIN  20
#define HH   128
#define EPSV 1e-5f

// ---------------- scratch ----------------
__device__ __align__(16) float g_yl[NN * HH];
__device__ __align__(16) float g_yr[NN * HH];
__device__ __align__(16) float g_pre[NN * HH];
__device__ __align__(16) float g_a20[NN * FIN];
__device__ int   g_deg[NN];
__device__ int   g_off[NN + 1];
__device__ int   g_csr[EE];
__device__ int   g_bsum[128];
__device__ float g_stats[3][2 * HH];
__device__ float g_normP[3][2 * HH];

typedef unsigned long long ull;

__device__ __forceinline__ ull pk2(float lo, float hi) {
    ull r; asm("mov.b64 %0, {%1,%2};" : "=l"(r) : "f"(lo), "f"(hi)); return r;
}
__device__ __forceinline__ void upk2(ull v, float& lo, float& hi) {
    asm("mov.b64 {%0,%1}, %2;" : "=f"(lo), "=f"(hi) : "l"(v));
}
__device__ __forceinline__ void fma2(ull& d, ull a, ull b) {
    asm("fma.rn.f32x2 %0, %1, %2, %0;" : "+l"(d) : "l"(a), "l"(b));
}
__device__ __forceinline__ float gelu_f(float x) {
    return 0.5f * x * (1.0f + erff(x * 0.70710678118654752f));
}

// ---------------- init + CSR build ----------------
__global__ void k_init() {
    int i = blockIdx.x * blockDim.x + threadIdx.x;
    if (i < NN) g_deg[i] = 0;
    if (i < 3 * 2 * HH) ((float*)g_stats)[i] = 0.f;
}
__global__ void k_hist(const int* __restrict__ ei) {
    int e = blockIdx.x * blockDim.x + threadIdx.x;
    if (e < EE) atomicAdd(&g_deg[ei[EE + e]], 1);
}
__global__ void k_scan1() {
    __shared__ int s[1024];
    int t = threadIdx.x;
    int i = blockIdx.x * 1024 + t;
    int v = (i < NN) ? g_deg[i] : 0;
    s[t] = v;
    __syncthreads();
#pragma unroll
    for (int d = 1; d < 1024; d <<= 1) {
        int x = (t >= d) ? s[t - d] : 0;
        __syncthreads();
        s[t] += x;
        __syncthreads();
    }
    if (i < NN) g_off[i + 1] = s[t];
    if (t == 1023) g_bsum[blockIdx.x] = s[1023];
}
__global__ void k_scan2(int nb) {
    __shared__ int s[128];
    int t = threadIdx.x;
    int v = (t < nb) ? g_bsum[t] : 0;
    s[t] = v;
    __syncthreads();
#pragma unroll
    for (int d = 1; d < 128; d <<= 1) {
        int x = (t >= d) ? s[t - d] : 0;
        __syncthreads();
        s[t] += x;
        __syncthreads();
    }
    if (t < nb) g_bsum[t] = s[t] - v;   // exclusive
}
__global__ void k_scan3() {
    int i = blockIdx.x * blockDim.x + threadIdx.x;
    if (i < NN) {
        int tot = g_off[i + 1] + g_bsum[i >> 10];
        g_off[i + 1] = tot;
        int d = g_deg[i];
        g_deg[i] = tot - d;
        if (i == 0) g_off[0] = 0;
    }
}
__global__ void k_fill(const int* __restrict__ ei) {
    int e = blockIdx.x * blockDim.x + threadIdx.x;
    if (e < EE) {
        int d = ei[EE + e];
        int pos = atomicAdd(&g_deg[d], 1);
        g_csr[pos] = ei[e];
    }
}

// ---------------- layer-0 aggregation (20 cols) ----------------
__global__ void k_agg20(const float* __restrict__ x) {
    int w = (blockIdx.x * blockDim.x + threadIdx.x) >> 5;
    int lane = threadIdx.x & 31;
    if (w >= NN) return;
    int off = g_off[w], end = g_off[w + 1];
    float acc = 0.f;
    for (int j = off; j < end; j += 32) {
        int idx = (j + lane < end) ? g_csr[j + lane] : 0;
        int cnt = min(32, end - j);
        int t = 0;
        for (; t + 4 <= cnt; t += 4) {
            int s0 = __shfl_sync(0xffffffffu, idx, t);
            int s1 = __shfl_sync(0xffffffffu, idx, t + 1);
            int s2 = __shfl_sync(0xffffffffu, idx, t + 2);
            int s3 = __shfl_sync(0xffffffffu, idx, t + 3);
            if (lane < FIN) {
                float v0 = x[s0 * FIN + lane], v1 = x[s1 * FIN + lane];
                float v2 = x[s2 * FIN + lane], v3 = x[s3 * FIN + lane];
                acc += (v0 + v1) + (v2 + v3);
            }
        }
        for (; t < cnt; t++) {
            int s = __shfl_sync(0xffffffffu, idx, t);
            if (lane < FIN) acc += x[s * FIN + lane];
        }
    }
    if (lane < FIN) {
        int deg = end - off;
        g_a20[w * FIN + lane] = acc * (deg > 0 ? 1.f / (float)deg : 0.f);
    }
}

// ---------------- layer-0 GEMM (K=20) + bias + stats ----------------
__global__ __launch_bounds__(256) void k_gemm0(
    const float* __restrict__ x, const float* __restrict__ Wl,
    const float* __restrict__ bl, const float* __restrict__ Wr)
{
    __shared__ float Wls[FIN][HH], Wrs[FIN][HH], bls[HH];
    __shared__ float As[64][FIN + 1], Xs[64][FIN + 1];
    __shared__ float red[16][HH];
    int tid = threadIdx.x;
    for (int e = tid; e < HH * FIN; e += 256) {
        int o = e / FIN, k = e % FIN;
        Wls[k][o] = Wl[e];
        Wrs[k][o] = Wr[e];
    }
    if (tid < HH) bls[tid] = bl[tid];
    int n0 = blockIdx.x * 64;
    for (int e = tid; e < 64 * FIN; e += 256) {
        int i = e / FIN, k = e % FIN;
        int n = n0 + i;
        As[i][k] = (n < NN) ? g_a20[n * FIN + k] : 0.f;
        Xs[i][k] = (n < NN) ? x[n * FIN + k] : 0.f;
    }
    __syncthreads();
    int tm = tid >> 4, tn = tid & 15;
    ull acc[4][4];
#pragma unroll
    for (int r = 0; r < 4; r++)
#pragma unroll
        for (int c = 0; c < 4; c++)
            acc[r][c] = pk2(bls[tn * 8 + 2 * c], bls[tn * 8 + 2 * c + 1]);
#pragma unroll 4
    for (int k = 0; k < FIN; k++) {
        const ull* wl = (const ull*)&Wls[k][tn * 8];
        const ull* wr = (const ull*)&Wrs[k][tn * 8];
#pragma unroll
        for (int r = 0; r < 4; r++) {
            ull a2 = pk2(As[tm * 4 + r][k], As[tm * 4 + r][k]);
            ull x2 = pk2(Xs[tm * 4 + r][k], Xs[tm * 4 + r][k]);
#pragma unroll
            for (int c = 0; c < 4; c++) { fma2(acc[r][c], a2, wl[c]); fma2(acc[r][c], x2, wr[c]); }
        }
    }
    float av[4][8];
    float s[8] = {0,0,0,0,0,0,0,0}, s2[8] = {0,0,0,0,0,0,0,0};
#pragma unroll
    for (int r = 0; r < 4; r++) {
#pragma unroll
        for (int c = 0; c < 4; c++) upk2(acc[r][c], av[r][2 * c], av[r][2 * c + 1]);
        int n = n0 + tm * 4 + r;
        if (n < NN) {
            float4* o4 = (float4*)(g_pre + n * HH + tn * 8);
            o4[0] = make_float4(av[r][0], av[r][1], av[r][2], av[r][3]);
            o4[1] = make_float4(av[r][4], av[r][5], av[r][6], av[r][7]);
#pragma unroll
            for (int j = 0; j < 8; j++) { s[j] += av[r][j]; s2[j] += av[r][j] * av[r][j]; }
        }
    }
#pragma unroll
    for (int j = 0; j < 8; j++) red[tm][tn * 8 + j] = s[j];
    __syncthreads();
    if (tid < HH) {
        float t = 0.f;
#pragma unroll
        for (int w = 0; w < 16; w++) t += red[w][tid];
        atomicAdd(&g_stats[0][tid], t);
    }
    __syncthreads();
#pragma unroll
    for (int j = 0; j < 8; j++) red[tm][tn * 8 + j] = s2[j];
    __syncthreads();
    if (tid < HH) {
        float t = 0.f;
#pragma unroll
        for (int w = 0; w < 16; w++) t += red[w][tid];
        atomicAdd(&g_stats[0][HH + tid], t);
    }
}

// ---------------- GraphNorm finish ----------------
__global__ void k_finish(const float* __restrict__ gw, const float* __restrict__ gb,
                         const float* __restrict__ ga, int L) {
    int c = threadIdx.x;
    float invn = 1.f / (float)NN;
    float m  = g_stats[L][c] * invn;
    float e2 = g_stats[L][HH + c] * invn;
    float a = ga[c];
    float var = fmaxf(e2 - m * m * (2.f * a - a * a), 0.f);
    float scale = gw[c] * rsqrtf(var + EPSV);
    g_normP[L][c] = scale;
    g_normP[L][HH + c] = gb[c] - a * m * scale;
}

// ---------------- fused norm+gelu A-load, dual-weight GEMM: yl,yr = gelu(norm(pre)) @ {Wl,Wr}^T ----------------
__global__ __launch_bounds__(512) void k_gemm256(
    const float* __restrict__ Wl, const float* __restrict__ Wr, int Lm1)
{
    __shared__ __align__(16) float As[16][132];
    __shared__ __align__(16) float Bs[16][260];
    __shared__ float nsc[HH], nsh[HH];
    int tid = threadIdx.x;
    if (tid < HH) { nsc[tid] = g_normP[Lm1][tid]; nsh[tid] = g_normP[Lm1][HH + tid]; }
    int m0 = blockIdx.x * 128;
    int lane = tid & 31, wp = tid >> 5;
    int am = tid >> 2, akc = tid & 3;
    const float4* P4  = (const float4*)g_pre;
    const float4* Wl4 = (const float4*)Wl;
    const float4* Wr4 = (const float4*)Wr;
    ull acc[8][4];
#pragma unroll
    for (int r = 0; r < 8; r++)
#pragma unroll
        for (int c = 0; c < 4; c++) acc[r][c] = 0ull;
    __syncthreads();
#pragma unroll 1
    for (int kt = 0; kt < 8; kt++) {
        __syncthreads();
        {   // A tile with fused norm+gelu
            int row = m0 + am;
            float4 v = make_float4(0.f, 0.f, 0.f, 0.f);
            if (row < NN) v = P4[row * 32 + kt * 4 + akc];
            int c = kt * 16 + akc * 4;
            As[akc * 4 + 0][am] = gelu_f(v.x * nsc[c + 0] + nsh[c + 0]);
            As[akc * 4 + 1][am] = gelu_f(v.y * nsc[c + 1] + nsh[c + 1]);
            As[akc * 4 + 2][am] = gelu_f(v.z * nsc[c + 2] + nsh[c + 2]);
            As[akc * 4 + 3][am] = gelu_f(v.w * nsc[c + 3] + nsh[c + 3]);
        }
#pragma unroll
        for (int q = 0; q < 2; q++) {   // B tile: [k][Wl cols | Wr cols]
            int id = tid + q * 512;
            int o = id >> 2, kc = id & 3;
            float4 w = (o < HH) ? Wl4[o * 32 + kt * 4 + kc]
                                : Wr4[(o - HH) * 32 + kt * 4 + kc];
            Bs[kc * 4 + 0][o] = w.x; Bs[kc * 4 + 1][o] = w.y;
            Bs[kc * 4 + 2][o] = w.z; Bs[kc * 4 + 3][o] = w.w;
        }
        __syncthreads();
#pragma unroll
        for (int k = 0; k < 16; k++) {
            float4 a0 = *(const float4*)&As[k][wp * 8];
            float4 a1 = *(const float4*)&As[k][wp * 8 + 4];
            const ull* br = (const ull*)&Bs[k][lane * 8];
            ull b0 = br[0], b1 = br[1], b2 = br[2], b3 = br[3];
            float ar[8] = {a0.x, a0.y, a0.z, a0.w, a1.x, a1.y, a1.z, a1.w};
#pragma unroll
            for (int r = 0; r < 8; r++) {
                ull a2 = pk2(ar[r], ar[r]);
                fma2(acc[r][0], a2, b0);
                fma2(acc[r][1], a2, b1);
                fma2(acc[r][2], a2, b2);
                fma2(acc[r][3], a2, b3);
            }
        }
    }
    float* dst = (lane < 16) ? g_yl : g_yr;
    int c0 = (lane & 15) * 8;
#pragma unroll
    for (int r = 0; r < 8; r++) {
        int row = m0 + wp * 8 + r;
        if (row < NN) {
            float4* o4 = (float4*)(dst + row * HH + c0);
            float4 v;
            upk2(acc[r][0], v.x, v.y); upk2(acc[r][1], v.z, v.w); o4[0] = v;
            upk2(acc[r][2], v.x, v.y); upk2(acc[r][3], v.z, v.w); o4[1] = v;
        }
    }
}

// ---------------- aggregation of yl + add yr + bias + stats ----------------
__global__ __launch_bounds__(256) void k_aggstats(const float* __restrict__ bl, int L)
{
    __shared__ float red[8][HH];
    int tid = threadIdx.x;
    int lane = tid & 31, wp = tid >> 5;
    const float4* yl4 = (const float4*)g_yl;
    const float4* yr4 = (const float4*)g_yr;
    float4 bias = ((const float4*)bl)[lane];
    float s[4] = {0, 0, 0, 0}, s2[4] = {0, 0, 0, 0};
    int gw = blockIdx.x * 8 + wp;
    const int stride = gridDim.x * 8;
    for (int w = gw; w < NN; w += stride) {
        int off = g_off[w], end = g_off[w + 1];
        float4 acc = make_float4(0.f, 0.f, 0.f, 0.f);
        for (int j = off; j < end; j += 32) {
            int idx = (j + lane < end) ? g_csr[j + lane] : 0;
            int cnt = min(32, end - j);
            int t = 0;
            for (; t + 4 <= cnt; t += 4) {
                int s0 = __shfl_sync(0xffffffffu, idx, t);
                int s1 = __shfl_sync(0xffffffffu, idx, t + 1);
                int s2i = __shfl_sync(0xffffffffu, idx, t + 2);
                int s3 = __shfl_sync(0xffffffffu, idx, t + 3);
                float4 v0 = yl4[s0 * 32 + lane];
                float4 v1 = yl4[s1 * 32 + lane];
                float4 v2 = yl4[s2i * 32 + lane];
                float4 v3 = yl4[s3 * 32 + lane];
                acc.x += (v0.x + v1.x) + (v2.x + v3.x);
                acc.y += (v0.y + v1.y) + (v2.y + v3.y);
                acc.z += (v0.z + v1.z) + (v2.z + v3.z);
                acc.w += (v0.w + v1.w) + (v2.w + v3.w);
            }
            for (; t < cnt; t++) {
                int sx = __shfl_sync(0xffffffffu, idx, t);
                float4 v = yl4[sx * 32 + lane];
                acc.x += v.x; acc.y += v.y; acc.z += v.z; acc.w += v.w;
            }
        }
        int deg = end - off;
        float inv = (deg > 0) ? 1.f / (float)deg : 0.f;
        float4 r = yr4[w * 32 + lane];
        r.x = acc.x * inv + r.x + bias.x;
        r.y = acc.y * inv + r.y + bias.y;
        r.z = acc.z * inv + r.z + bias.z;
        r.w = acc.w * inv + r.w + bias.w;
        ((float4*)g_pre)[w * 32 + lane] = r;
        s[0] += r.x; s2[0] += r.x * r.x;
        s[1] += r.y; s2[1] += r.y * r.y;
        s[2] += r.z; s2[2] += r.z * r.z;
        s[3] += r.w; s2[3] += r.w * r.w;
    }
#pragma unroll
    for (int i = 0; i < 4; i++) red[wp][lane * 4 + i] = s[i];
    __syncthreads();
    if (tid < HH) {
        float t = 0.f;
#pragma unroll
        for (int w = 0; w < 8; w++) t += red[w][tid];
        atomicAdd(&g_stats[L][tid], t);
    }
    __syncthreads();
#pragma unroll
    for (int i = 0; i < 4; i++) red[wp][lane * 4 + i] = s2[i];
    __syncthreads();
    if (tid < HH) {
        float t = 0.f;
#pragma unroll
        for (int w = 0; w < 8; w++) t += red[w][tid];
        atomicAdd(&g_stats[L][HH + tid], t);
    }
}

// ---------------- fused MLP head with norm+gelu on input ----------------
__global__ __launch_bounds__(128) void k_mlp(
    const float* __restrict__ hW1, const float* __restrict__ hb1,
    const float* __restrict__ hW2, const float* __restrict__ hb2,
    const float* __restrict__ hW3, const float* __restrict__ hb3,
    float* __restrict__ out)
{
    extern __shared__ float sm[];
    float* W1t = sm;                 // [128][64]
    float* W2t = W1t + 128 * 64;     // [64][32]
    float* w3  = W2t + 64 * 32;      // [32]
    float* b1  = w3 + 32;            // [64]
    float* b2  = b1 + 64;            // [32]
    float* nsc = b2 + 32;            // [128]
    float* nsh = nsc + 128;          // [128]
    float* hs  = nsh + 128;          // [128][129]

    int tid = threadIdx.x;
    for (int e = tid; e < 8192; e += 128) { int o = e >> 7, k = e & 127; W1t[k * 64 + o] = hW1[e]; }
    for (int e = tid; e < 2048; e += 128) { int o = e >> 6, k = e & 63;  W2t[k * 32 + o] = hW2[e]; }
    if (tid < 32) w3[tid] = hW3[tid];
    if (tid < 64) b1[tid] = hb1[tid];
    if (tid < 32) b2[tid] = hb2[tid];
    nsc[tid] = g_normP[2][tid];
    nsh[tid] = g_normP[2][HH + tid];
    __syncthreads();

    int n0 = blockIdx.x * 128;
    const float4* p4 = (const float4*)g_pre;
    for (int e = tid; e < 128 * 32; e += 128) {
        int r = e >> 5, cc = e & 31;
        int n = n0 + r;
        float4 v = make_float4(0.f, 0.f, 0.f, 0.f);
        if (n < NN) v = p4[n * 32 + cc];
        int c = cc * 4;
        hs[(c + 0) * 129 + r] = gelu_f(v.x * nsc[c + 0] + nsh[c + 0]);
        hs[(c + 1) * 129 + r] = gelu_f(v.y * nsc[c + 1] + nsh[c + 1]);
        hs[(c + 2) * 129 + r] = gelu_f(v.z * nsc[c + 2] + nsh[c + 2]);
        hs[(c + 3) * 129 + r] = gelu_f(v.w * nsc[c + 3] + nsh[c + 3]);
    }
    __syncthreads();

    int n = n0 + tid;
    if (n >= NN) return;

    ull acc1[32];
#pragma unroll
    for (int i = 0; i < 32; i++) acc1[i] = pk2(b1[2 * i], b1[2 * i + 1]);
    for (int k = 0; k < 128; k++) {
        float hv = hs[k * 129 + tid];
        ull a2 = pk2(hv, hv);
        const ull* wr = (const ull*)(W1t + k * 64);
#pragma unroll
        for (int i = 0; i < 32; i++) fma2(acc1[i], a2, wr[i]);
    }
    float y1[64];
#pragma unroll
    for (int i = 0; i < 32; i++) {
        float lo, hi;
        upk2(acc1[i], lo, hi);
        y1[2 * i] = gelu_f(lo);
        y1[2 * i + 1] = gelu_f(hi);
    }
    ull acc2[16];
#pragma unroll
    for (int i = 0; i < 16; i++) acc2[i] = pk2(b2[2 * i], b2[2 * i + 1]);
#pragma unroll 4
    for (int k = 0; k < 64; k++) {
        ull a2 = pk2(y1[k], y1[k]);
        const ull* wr = (const ull*)(W2t + k * 32);
#pragma unroll
        for (int i = 0; i < 16; i++) fma2(acc2[i], a2, wr[i]);
    }
    float s = 0.f;
#pragma unroll
    for (int i = 0; i < 16; i++) {
        float lo, hi;
        upk2(acc2[i], lo, hi);
        s += gelu_f(lo) * w3[2 * i] + gelu_f(hi) * w3[2 * i + 1];
    }
    s += hb3[0];
    out[n] = 1.f / (1.f + expf(-s));
}

// ---------------- launch ----------------
extern "C" void kernel_launch(void* const* d_in, const int* in_sizes, int n_in,
                              void* d_out, int out_size)
{
    const float* x   = (const float*)d_in[0];
    const int*   ei  = (const int*)d_in[1];
    const float* Wl[3] = {(const float*)d_in[2],  (const float*)d_in[8],  (const float*)d_in[14]};
    const float* bl[3] = {(const float*)d_in[3],  (const float*)d_in[9],  (const float*)d_in[15]};
    const float* Wr[3] = {(const float*)d_in[4],  (const float*)d_in[10], (const float*)d_in[16]};
    const float* gw[3] = {(const float*)d_in[5],  (const float*)d_in[11], (const float*)d_in[17]};
    const float* gb[3] = {(const float*)d_in[6],  (const float*)d_in[12], (const float*)d_in[18]};
    const float* ga[3] = {(const float*)d_in[7],  (const float*)d_in[13], (const float*)d_in[19]};
    const float* hW1 = (const float*)d_in[20];
    const float* hb1 = (const float*)d_in[21];
    const float* hW2 = (const float*)d_in[22];
    const float* hb2 = (const float*)d_in[23];
    const float* hW3 = (const float*)d_in[24];
    const float* hb3 = (const float*)d_in[25];
    float* out = (float*)d_out;

    const int SCAN_BLOCKS = (NN + 1023) / 1024;      // 98
    const int MLP_SMEM = (8192 + 2048 + 32 + 64 + 32 + 256 + 128 * 129) * 4;
    cudaFuncSetAttribute(k_mlp, cudaFuncAttributeMaxDynamicSharedMemorySize, MLP_SMEM);

    // CSR build
    k_init<<<(NN + 255) / 256, 256>>>();
    k_hist<<<(EE + 255) / 256, 256>>>(ei);
    k_scan1<<<SCAN_BLOCKS, 1024>>>();
    k_scan2<<<1, 128>>>(SCAN_BLOCKS);
    k_scan3<<<(NN + 255) / 256, 256>>>();
    k_fill<<<(EE + 255) / 256, 256>>>(ei);

    // layer 0
    k_agg20<<<(NN * 32 + 255) / 256, 256>>>(x);
    k_gemm0<<<(NN + 63) / 64, 256>>>(x, Wl[0], bl[0], Wr[0]);
    k_finish<<<1, 128>>>(gw[0], gb[0], ga[0], 0);

    // layers 1, 2: gemm (norm+gelu fused on A) -> agg+add+bias+stats -> finish
    for (int L = 1; L <= 2; L++) {
        k_gemm256<<<(NN + 127) / 128, 512>>>(Wl[L], Wr[L], L - 1);
        k_aggstats<<<782, 256>>>(bl[L], L);
        k_finish<<<1, 128>>>(gw[L], gb[L], ga[L], L);
    }

    // MLP head (norm+gelu fused on input)
    k_mlp<<<(NN + 127) / 128, 128, MLP_SMEM>>>(hW1, hb1, hW2, hb2, hW3, hb3, out);
}

// round 4
// speedup vs baseline: 1.4135x; 1.1743x over previous
#include <cuda_runtime.h>
#include <math.h>

#define NN   100000
#define EE   1600000
#define FIN  20
#define HH   128
#define EPSV 1e-5f
#define NTILES 782            // ceil(NN/128)

// ---------------- scratch ----------------
__device__ __align__(16) float g_yl[NN * HH];
__device__ __align__(16) float g_yr[NN * HH];
__device__ __align__(16) float g_pre[NN * HH];
__device__ __align__(16) float g_a20[NN * FIN];
__device__ int   g_deg[NN];
__device__ int   g_off[NN + 1];
__device__ int   g_csr[EE];
__device__ int   g_bsum[128];
__device__ float g_stats[3][2 * HH];
__device__ float g_normP[3][2 * HH];

typedef unsigned long long ull;
typedef unsigned int uint;

__device__ __forceinline__ ull pk2(float lo, float hi) {
    ull r; asm("mov.b64 %0, {%1,%2};" : "=l"(r) : "f"(lo), "f"(hi)); return r;
}
__device__ __forceinline__ void upk2(ull v, float& lo, float& hi) {
    asm("mov.b64 {%0,%1}, %2;" : "=f"(lo), "=f"(hi) : "l"(v));
}
__device__ __forceinline__ void fma2(ull& d, ull a, ull b) {
    asm("fma.rn.f32x2 %0, %1, %2, %0;" : "+l"(d) : "l"(a), "l"(b));
}
__device__ __forceinline__ float gelu_f(float x) {
    return 0.5f * x * (1.0f + erff(x * 0.70710678118654752f));
}
__device__ __forceinline__ uint cvt_tf32(float v) {
    uint r; asm("cvt.rna.tf32.f32 %0, %1;" : "=r"(r) : "f"(v)); return r;
}
__device__ __forceinline__ void mma_tf32(float* d, uint a0, uint a1, uint a2, uint a3,
                                         uint b0, uint b1) {
    asm volatile(
        "mma.sync.aligned.m16n8k8.row.col.f32.tf32.tf32.f32 "
        "{%0,%1,%2,%3}, {%4,%5,%6,%7}, {%8,%9}, {%0,%1,%2,%3};"
        : "+f"(d[0]), "+f"(d[1]), "+f"(d[2]), "+f"(d[3])
        : "r"(a0), "r"(a1), "r"(a2), "r"(a3), "r"(b0), "r"(b1));
}

// ---------------- init + CSR build ----------------
__global__ void k_init() {
    int i = blockIdx.x * blockDim.x + threadIdx.x;
    if (i < NN) g_deg[i] = 0;
    if (i < 3 * 2 * HH) ((float*)g_stats)[i] = 0.f;
}
__global__ void k_hist(const int* __restrict__ ei) {
    int e = blockIdx.x * blockDim.x + threadIdx.x;
    if (e < EE) atomicAdd(&g_deg[ei[EE + e]], 1);
}
__global__ void k_scan1() {
    __shared__ int s[1024];
    int t = threadIdx.x;
    int i = blockIdx.x * 1024 + t;
    int v = (i < NN) ? g_deg[i] : 0;
    s[t] = v;
    __syncthreads();
#pragma unroll
    for (int d = 1; d < 1024; d <<= 1) {
        int x = (t >= d) ? s[t - d] : 0;
        __syncthreads();
        s[t] += x;
        __syncthreads();
    }
    if (i < NN) g_off[i + 1] = s[t];
    if (t == 1023) g_bsum[blockIdx.x] = s[1023];
}
__global__ void k_scan2(int nb) {
    __shared__ int s[128];
    int t = threadIdx.x;
    int v = (t < nb) ? g_bsum[t] : 0;
    s[t] = v;
    __syncthreads();
#pragma unroll
    for (int d = 1; d < 128; d <<= 1) {
        int x = (t >= d) ? s[t - d] : 0;
        __syncthreads();
        s[t] += x;
        __syncthreads();
    }
    if (t < nb) g_bsum[t] = s[t] - v;
}
__global__ void k_scan3() {
    int i = blockIdx.x * blockDim.x + threadIdx.x;
    if (i < NN) {
        int tot = g_off[i + 1] + g_bsum[i >> 10];
        g_off[i + 1] = tot;
        int d = g_deg[i];
        g_deg[i] = tot - d;
        if (i == 0) g_off[0] = 0;
    }
}
__global__ void k_fill(const int* __restrict__ ei) {
    int e = blockIdx.x * blockDim.x + threadIdx.x;
    if (e < EE) {
        int d = ei[EE + e];
        int pos = atomicAdd(&g_deg[d], 1);
        g_csr[pos] = ei[e];
    }
}

// ---------------- layer-0 aggregation (20 cols) ----------------
__global__ void k_agg20(const float* __restrict__ x) {
    int w = (blockIdx.x * blockDim.x + threadIdx.x) >> 5;
    int lane = threadIdx.x & 31;
    if (w >= NN) return;
    int off = g_off[w], end = g_off[w + 1];
    float acc = 0.f;
    for (int j = off; j < end; j += 32) {
        int idx = (j + lane < end) ? g_csr[j + lane] : 0;
        int cnt = min(32, end - j);
        int t = 0;
        for (; t + 4 <= cnt; t += 4) {
            int s0 = __shfl_sync(0xffffffffu, idx, t);
            int s1 = __shfl_sync(0xffffffffu, idx, t + 1);
            int s2 = __shfl_sync(0xffffffffu, idx, t + 2);
            int s3 = __shfl_sync(0xffffffffu, idx, t + 3);
            if (lane < FIN) {
                float v0 = x[s0 * FIN + lane], v1 = x[s1 * FIN + lane];
                float v2 = x[s2 * FIN + lane], v3 = x[s3 * FIN + lane];
                acc += (v0 + v1) + (v2 + v3);
            }
        }
        for (; t < cnt; t++) {
            int s = __shfl_sync(0xffffffffu, idx, t);
            if (lane < FIN) acc += x[s * FIN + lane];
        }
    }
    if (lane < FIN) {
        int deg = end - off;
        g_a20[w * FIN + lane] = acc * (deg > 0 ? 1.f / (float)deg : 0.f);
    }
}

// ---------------- layer-0 GEMM (K=20) + bias + stats ----------------
__global__ __launch_bounds__(256) void k_gemm0(
    const float* __restrict__ x, const float* __restrict__ Wl,
    const float* __restrict__ bl, const float* __restrict__ Wr)
{
    __shared__ float Wls[FIN][HH], Wrs[FIN][HH], bls[HH];
    __shared__ float As[64][FIN + 1], Xs[64][FIN + 1];
    __shared__ float red[16][HH];
    int tid = threadIdx.x;
    for (int e = tid; e < HH * FIN; e += 256) {
        int o = e / FIN, k = e % FIN;
        Wls[k][o] = Wl[e];
        Wrs[k][o] = Wr[e];
    }
    if (tid < HH) bls[tid] = bl[tid];
    int n0 = blockIdx.x * 64;
    for (int e = tid; e < 64 * FIN; e += 256) {
        int i = e / FIN, k = e % FIN;
        int n = n0 + i;
        As[i][k] = (n < NN) ? g_a20[n * FIN + k] : 0.f;
        Xs[i][k] = (n < NN) ? x[n * FIN + k] : 0.f;
    }
    __syncthreads();
    int tm = tid >> 4, tn = tid & 15;
    ull acc[4][4];
#pragma unroll
    for (int r = 0; r < 4; r++)
#pragma unroll
        for (int c = 0; c < 4; c++)
            acc[r][c] = pk2(bls[tn * 8 + 2 * c], bls[tn * 8 + 2 * c + 1]);
#pragma unroll 4
    for (int k = 0; k < FIN; k++) {
        const ull* wl = (const ull*)&Wls[k][tn * 8];
        const ull* wr = (const ull*)&Wrs[k][tn * 8];
#pragma unroll
        for (int r = 0; r < 4; r++) {
            ull a2 = pk2(As[tm * 4 + r][k], As[tm * 4 + r][k]);
            ull x2 = pk2(Xs[tm * 4 + r][k], Xs[tm * 4 + r][k]);
#pragma unroll
            for (int c = 0; c < 4; c++) { fma2(acc[r][c], a2, wl[c]); fma2(acc[r][c], x2, wr[c]); }
        }
    }
    float av[4][8];
    float s[8] = {0,0,0,0,0,0,0,0}, s2[8] = {0,0,0,0,0,0,0,0};
#pragma unroll
    for (int r = 0; r < 4; r++) {
#pragma unroll
        for (int c = 0; c < 4; c++) upk2(acc[r][c], av[r][2 * c], av[r][2 * c + 1]);
        int n = n0 + tm * 4 + r;
        if (n < NN) {
            float4* o4 = (float4*)(g_pre + n * HH + tn * 8);
            o4[0] = make_float4(av[r][0], av[r][1], av[r][2], av[r][3]);
            o4[1] = make_float4(av[r][4], av[r][5], av[r][6], av[r][7]);
#pragma unroll
            for (int j = 0; j < 8; j++) { s[j] += av[r][j]; s2[j] += av[r][j] * av[r][j]; }
        }
    }
#pragma unroll
    for (int j = 0; j < 8; j++) red[tm][tn * 8 + j] = s[j];
    __syncthreads();
    if (tid < HH) {
        float t = 0.f;
#pragma unroll
        for (int w = 0; w < 16; w++) t += red[w][tid];
        atomicAdd(&g_stats[0][tid], t);
    }
    __syncthreads();
#pragma unroll
    for (int j = 0; j < 8; j++) red[tm][tn * 8 + j] = s2[j];
    __syncthreads();
    if (tid < HH) {
        float t = 0.f;
#pragma unroll
        for (int w = 0; w < 16; w++) t += red[w][tid];
        atomicAdd(&g_stats[0][HH + tid], t);
    }
}

// ---------------- GraphNorm finish ----------------
__global__ void k_finish(const float* __restrict__ gw, const float* __restrict__ gb,
                         const float* __restrict__ ga, int L) {
    int c = threadIdx.x;
    float invn = 1.f / (float)NN;
    float m  = g_stats[L][c] * invn;
    float e2 = g_stats[L][HH + c] * invn;
    float a = ga[c];
    float var = fmaxf(e2 - m * m * (2.f * a - a * a), 0.f);
    float scale = gw[c] * rsqrtf(var + EPSV);
    g_normP[L][c] = scale;
    g_normP[L][HH + c] = gb[c] - a * m * scale;
}

// ---------------- TF32 mma.sync dual GEMM: yl,yr = gelu(norm(pre)) @ {Wl,Wr}^T ----------------
// persistent blocks; weights staged once per block; A tile staged per M-tile (norm+gelu fused).
// smem: Ws [256][132] tf32 | As [128][132] tf32 | nsc [128] | nsh [128]
#define OFF_WS   0
#define OFF_AS   (256 * 132 * 4)
#define OFF_NSC  (OFF_AS + 128 * 132 * 4)
#define OFF_NSH  (OFF_NSC + 512)
#define MMA_SMEM (OFF_NSH + 512)

__global__ __launch_bounds__(256) void k_gemm_mma(
    const float* __restrict__ Wl, const float* __restrict__ Wr, int Lm1)
{
    extern __shared__ char sm[];
    uint*  Ws  = (uint*)(sm + OFF_WS);
    uint*  As  = (uint*)(sm + OFF_AS);
    float* nsc = (float*)(sm + OFF_NSC);
    float* nsh = (float*)(sm + OFF_NSH);
    int tid = threadIdx.x;
    int wid = tid >> 5, lane = tid & 31;
    int tq = lane >> 2, tr = lane & 3;

    if (tid < HH) { nsc[tid] = g_normP[Lm1][tid]; nsh[tid] = g_normP[Lm1][HH + tid]; }

    // stage weights once: rows 0..127 = Wl, 128..255 = Wr (tf32)
    for (int e = tid; e < 256 * 32; e += 256) {
        int r = e >> 5, c4 = e & 31;
        const float4* src = (const float4*)((r < 128) ? Wl : Wr);
        float4 v = src[(r & 127) * 32 + c4];
        uint* d = Ws + r * 132 + c4 * 4;
        d[0] = cvt_tf32(v.x); d[1] = cvt_tf32(v.y);
        d[2] = cvt_tf32(v.z); d[3] = cvt_tf32(v.w);
    }

    const float4* P4 = (const float4*)g_pre;

    for (int tile = blockIdx.x; tile < NTILES; tile += gridDim.x) {
        int m0 = tile * 128;
        __syncthreads();   // previous iteration's compute done before restaging A
        // stage A tile: norm + gelu + tf32
        for (int e = tid; e < 128 * 32; e += 256) {
            int r = e >> 5, c4 = e & 31;
            int row = m0 + r;
            float4 v = make_float4(0.f, 0.f, 0.f, 0.f);
            if (row < NN) v = P4[row * 32 + c4];
            int c = c4 * 4;
            uint* d = As + r * 132 + c;
            d[0] = cvt_tf32(gelu_f(v.x * nsc[c + 0] + nsh[c + 0]));
            d[1] = cvt_tf32(gelu_f(v.y * nsc[c + 1] + nsh[c + 1]));
            d[2] = cvt_tf32(gelu_f(v.z * nsc[c + 2] + nsh[c + 2]));
            d[3] = cvt_tf32(gelu_f(v.w * nsc[c + 3] + nsh[c + 3]));
        }
        __syncthreads();

        int mrow = wid * 16 + tq;             // warp covers rows wid*16 .. +15
        const uint* Arow0 = As + mrow * 132;
        const uint* Arow1 = As + (mrow + 8) * 132;
#pragma unroll 1
        for (int chunk = 0; chunk < 4; chunk++) {
            float dfr[8][4];
#pragma unroll
            for (int j = 0; j < 8; j++)
#pragma unroll
                for (int c = 0; c < 4; c++) dfr[j][c] = 0.f;
#pragma unroll
            for (int k8 = 0; k8 < 16; k8++) {
                int kk = k8 * 8;
                uint a0 = Arow0[kk + tr];
                uint a1 = Arow1[kk + tr];
                uint a2 = Arow0[kk + 4 + tr];
                uint a3 = Arow1[kk + 4 + tr];
                const uint* wb = Ws + (chunk * 64 + tq) * 132 + kk + tr;
#pragma unroll
                for (int j = 0; j < 8; j++) {
                    uint b0 = wb[j * 8 * 132];
                    uint b1 = wb[j * 8 * 132 + 4];
                    mma_tf32(dfr[j], a0, a1, a2, a3, b0, b1);
                }
            }
            // epilogue: write D chunk directly (cols <128 -> yl, else yr)
            int row0 = m0 + mrow;
#pragma unroll
            for (int j = 0; j < 8; j++) {
                int gcol = chunk * 64 + j * 8 + tr * 2;
                float* base = (gcol < HH) ? g_yl : g_yr;
                int col = gcol & (HH - 1);
                if (row0 < NN)
                    *(float2*)(base + row0 * HH + col) = make_float2(dfr[j][0], dfr[j][1]);
                if (row0 + 8 < NN)
                    *(float2*)(base + (row0 + 8) * HH + col) = make_float2(dfr[j][2], dfr[j][3]);
            }
        }
    }
}

// ---------------- aggregation of yl + add yr + bias + stats ----------------
__global__ __launch_bounds__(256) void k_aggstats(const float* __restrict__ bl, int L)
{
    __shared__ float red[8][HH];
    int tid = threadIdx.x;
    int lane = tid & 31, wp = tid >> 5;
    const float4* yl4 = (const float4*)g_yl;
    const float4* yr4 = (const float4*)g_yr;
    float4 bias = ((const float4*)bl)[lane];
    float s[4] = {0, 0, 0, 0}, s2[4] = {0, 0, 0, 0};
    int gw = blockIdx.x * 8 + wp;
    const int stride = gridDim.x * 8;
    for (int w = gw; w < NN; w += stride) {
        int off = g_off[w], end = g_off[w + 1];
        float4 acc = make_float4(0.f, 0.f, 0.f, 0.f);
        for (int j = off; j < end; j += 32) {
            int idx = (j + lane < end) ? g_csr[j + lane] : 0;
            int cnt = min(32, end - j);
            int t = 0;
            for (; t + 4 <= cnt; t += 4) {
                int s0 = __shfl_sync(0xffffffffu, idx, t);
                int s1 = __shfl_sync(0xffffffffu, idx, t + 1);
                int s2i = __shfl_sync(0xffffffffu, idx, t + 2);
                int s3 = __shfl_sync(0xffffffffu, idx, t + 3);
                float4 v0 = yl4[s0 * 32 + lane];
                float4 v1 = yl4[s1 * 32 + lane];
                float4 v2 = yl4[s2i * 32 + lane];
                float4 v3 = yl4[s3 * 32 + lane];
                acc.x += (v0.x + v1.x) + (v2.x + v3.x);
                acc.y += (v0.y + v1.y) + (v2.y + v3.y);
                acc.z += (v0.z + v1.z) + (v2.z + v3.z);
                acc.w += (v0.w + v1.w) + (v2.w + v3.w);
            }
            for (; t < cnt; t++) {
                int sx = __shfl_sync(0xffffffffu, idx, t);
                float4 v = yl4[sx * 32 + lane];
                acc.x += v.x; acc.y += v.y; acc.z += v.z; acc.w += v.w;
            }
        }
        int deg = end - off;
        float inv = (deg > 0) ? 1.f / (float)deg : 0.f;
        float4 r = yr4[w * 32 + lane];
        r.x = acc.x * inv + r.x + bias.x;
        r.y = acc.y * inv + r.y + bias.y;
        r.z = acc.z * inv + r.z + bias.z;
        r.w = acc.w * inv + r.w + bias.w;
        ((float4*)g_pre)[w * 32 + lane] = r;
        s[0] += r.x; s2[0] += r.x * r.x;
        s[1] += r.y; s2[1] += r.y * r.y;
        s[2] += r.z; s2[2] += r.z * r.z;
        s[3] += r.w; s2[3] += r.w * r.w;
    }
#pragma unroll
    for (int i = 0; i < 4; i++) red[wp][lane * 4 + i] = s[i];
    __syncthreads();
    if (tid < HH) {
        float t = 0.f;
#pragma unroll
        for (int w = 0; w < 8; w++) t += red[w][tid];
        atomicAdd(&g_stats[L][tid], t);
    }
    __syncthreads();
#pragma unroll
    for (int i = 0; i < 4; i++) red[wp][lane * 4 + i] = s2[i];
    __syncthreads();
    if (tid < HH) {
        float t = 0.f;
#pragma unroll
        for (int w = 0; w < 8; w++) t += red[w][tid];
        atomicAdd(&g_stats[L][HH + tid], t);
    }
}

// ---------------- fused MLP head with norm+gelu on input ----------------
__global__ __launch_bounds__(128) void k_mlp(
    const float* __restrict__ hW1, const float* __restrict__ hb1,
    const float* __restrict__ hW2, const float* __restrict__ hb2,
    const float* __restrict__ hW3, const float* __restrict__ hb3,
    float* __restrict__ out)
{
    extern __shared__ float smf[];
    float* W1t = smf;                // [128][64]
    float* W2t = W1t + 128 * 64;     // [64][32]
    float* w3  = W2t + 64 * 32;      // [32]
    float* b1  = w3 + 32;            // [64]
    float* b2  = b1 + 64;            // [32]
    float* nsc = b2 + 32;            // [128]
    float* nsh = nsc + 128;          // [128]
    float* hs  = nsh + 128;          // [128][129]

    int tid = threadIdx.x;
    for (int e = tid; e < 8192; e += 128) { int o = e >> 7, k = e & 127; W1t[k * 64 + o] = hW1[e]; }
    for (int e = tid; e < 2048; e += 128) { int o = e >> 6, k = e & 63;  W2t[k * 32 + o] = hW2[e]; }
    if (tid < 32) w3[tid] = hW3[tid];
    if (tid < 64) b1[tid] = hb1[tid];
    if (tid < 32) b2[tid] = hb2[tid];
    nsc[tid] = g_normP[2][tid];
    nsh[tid] = g_normP[2][HH + tid];
    __syncthreads();

    int n0 = blockIdx.x * 128;
    const float4* p4 = (const float4*)g_pre;
    for (int e = tid; e < 128 * 32; e += 128) {
        int r = e >> 5, cc = e & 31;
        int n = n0 + r;
        float4 v = make_float4(0.f, 0.f, 0.f, 0.f);
        if (n < NN) v = p4[n * 32 + cc];
        int c = cc * 4;
        hs[(c + 0) * 129 + r] = gelu_f(v.x * nsc[c + 0] + nsh[c + 0]);
        hs[(c + 1) * 129 + r] = gelu_f(v.y * nsc[c + 1] + nsh[c + 1]);
        hs[(c + 2) * 129 + r] = gelu_f(v.z * nsc[c + 2] + nsh[c + 2]);
        hs[(c + 3) * 129 + r] = gelu_f(v.w * nsc[c + 3] + nsh[c + 3]);
    }
    __syncthreads();

    int n = n0 + tid;
    if (n >= NN) return;

    ull acc1[32];
#pragma unroll
    for (int i = 0; i < 32; i++) acc1[i] = pk2(b1[2 * i], b1[2 * i + 1]);
    for (int k = 0; k < 128; k++) {
        float hv = hs[k * 129 + tid];
        ull a2 = pk2(hv, hv);
        const ull* wr = (const ull*)(W1t + k * 64);
#pragma unroll
        for (int i = 0; i < 32; i++) fma2(acc1[i], a2, wr[i]);
    }
    float y1[64];
#pragma unroll
    for (int i = 0; i < 32; i++) {
        float lo, hi;
        upk2(acc1[i], lo, hi);
        y1[2 * i] = gelu_f(lo);
        y1[2 * i + 1] = gelu_f(hi);
    }
    ull acc2[16];
#pragma unroll
    for (int i = 0; i < 16; i++) acc2[i] = pk2(b2[2 * i], b2[2 * i + 1]);
#pragma unroll 4
    for (int k = 0; k < 64; k++) {
        ull a2 = pk2(y1[k], y1[k]);
        const ull* wr = (const ull*)(W2t + k * 32);
#pragma unroll
        for (int i = 0; i < 16; i++) fma2(acc2[i], a2, wr[i]);
    }
    float s = 0.f;
#pragma unroll
    for (int i = 0; i < 16; i++) {
        float lo, hi;
        upk2(acc2[i], lo, hi);
        s += gelu_f(lo) * w3[2 * i] + gelu_f(hi) * w3[2 * i + 1];
    }
    s += hb3[0];
    out[n] = 1.f / (1.f + expf(-s));
}

// ---------------- launch ----------------
extern "C" void kernel_launch(void* const* d_in, const int* in_sizes, int n_in,
                              void* d_out, int out_size)
{
    const float* x   = (const float*)d_in[0];
    const int*   ei  = (const int*)d_in[1];
    const float* Wl[3] = {(const float*)d_in[2],  (const float*)d_in[8],  (const float*)d_in[14]};
    const float* bl[3] = {(const float*)d_in[3],  (const float*)d_in[9],  (const float*)d_in[15]};
    const float* Wr[3] = {(const float*)d_in[4],  (const float*)d_in[10], (const float*)d_in[16]};
    const float* gw[3] = {(const float*)d_in[5],  (const float*)d_in[11], (const float*)d_in[17]};
    const float* gb[3] = {(const float*)d_in[6],  (const float*)d_in[12], (const float*)d_in[18]};
    const float* ga[3] = {(const float*)d_in[7],  (const float*)d_in[13], (const float*)d_in[19]};
    const float* hW1 = (const float*)d_in[20];
    const float* hb1 = (const float*)d_in[21];
    const float* hW2 = (const float*)d_in[22];
    const float* hb2 = (const float*)d_in[23];
    const float* hW3 = (const float*)d_in[24];
    const float* hb3 = (const float*)d_in[25];
    float* out = (float*)d_out;

    const int SCAN_BLOCKS = (NN + 1023) / 1024;      // 98
    const int MLP_SMEM = (8192 + 2048 + 32 + 64 + 32 + 256 + 128 * 129) * 4;
    cudaFuncSetAttribute(k_mlp, cudaFuncAttributeMaxDynamicSharedMemorySize, MLP_SMEM);
    cudaFuncSetAttribute(k_gemm_mma, cudaFuncAttributeMaxDynamicSharedMemorySize, MMA_SMEM);

    // CSR build
    k_init<<<(NN + 255) / 256, 256>>>();
    k_hist<<<(EE + 255) / 256, 256>>>(ei);
    k_scan1<<<SCAN_BLOCKS, 1024>>>();
    k_scan2<<<1, 128>>>(SCAN_BLOCKS);
    k_scan3<<<(NN + 255) / 256, 256>>>();
    k_fill<<<(EE + 255) / 256, 256>>>(ei);

    // layer 0
    k_agg20<<<(NN * 32 + 255) / 256, 256>>>(x);
    k_gemm0<<<(NN + 63) / 64, 256>>>(x, Wl[0], bl[0], Wr[0]);
    k_finish<<<1, 128>>>(gw[0], gb[0], ga[0], 0);

    // layers 1, 2: tf32 mma gemm (norm+gelu fused on A) -> agg+add+bias+stats -> finish
    for (int L = 1; L <= 2; L++) {
        k_gemm_mma<<<148, 256, MMA_SMEM>>>(Wl[L], Wr[L], L - 1);
        k_aggstats<<<782, 256>>>(bl[L], L);
        k_finish<<<1, 128>>>(gw[L], gb[L], ga[L], L);
    }

    // MLP head (norm+gelu fused on input)
    k_mlp<<<(NN + 127) / 128, 128, MLP_SMEM>>>(hW1, hb1, hW2, hb2, hW3, hb3, out);
}

// round 5
// speedup vs baseline: 1.5607x; 1.1041x over previous
#include <cuda_runtime.h>
#include <cuda_fp16.h>
#include <math.h>

#define NN   100000
#define EE   1600000
#define FIN  20
#define HH   128
#define EPSV 1e-5f
#define NTILES 782            // ceil(NN/128)

// ---------------- scratch ----------------
__device__ __align__(16) unsigned int g_yl16[NN * 64];   // fp16x2: [N][64] half2 = 128 ch
__device__ __align__(16) float g_yr[NN * HH];
__device__ __align__(16) float g_pre[NN * HH];
__device__ __align__(16) float g_a20[NN * FIN];
__device__ int   g_deg[NN];
__device__ int   g_off[NN + 1];
__device__ int   g_csr[EE];
__device__ int   g_bsum[128];
__device__ float g_stats[3][2 * HH];
__device__ float g_normP[3][2 * HH];

typedef unsigned long long ull;
typedef unsigned int uint;

__device__ __forceinline__ ull pk2(float lo, float hi) {
    ull r; asm("mov.b64 %0, {%1,%2};" : "=l"(r) : "f"(lo), "f"(hi)); return r;
}
__device__ __forceinline__ void upk2(ull v, float& lo, float& hi) {
    asm("mov.b64 {%0,%1}, %2;" : "=f"(lo), "=f"(hi) : "l"(v));
}
__device__ __forceinline__ void fma2(ull& d, ull a, ull b) {
    asm("fma.rn.f32x2 %0, %1, %2, %0;" : "+l"(d) : "l"(a), "l"(b));
}
__device__ __forceinline__ float gelu_f(float x) {
    return 0.5f * x * (1.0f + erff(x * 0.70710678118654752f));
}
__device__ __forceinline__ uint cvt_tf32(float v) {
    uint r; asm("cvt.rna.tf32.f32 %0, %1;" : "=r"(r) : "f"(v)); return r;
}
__device__ __forceinline__ uint pack_h2(float lo, float hi) {
    uint r; asm("cvt.rn.f16x2.f32 %0, %2, %1;" : "=r"(r) : "f"(lo), "f"(hi)); return r;
}
__device__ __forceinline__ void mma_tf32(float* d, uint a0, uint a1, uint a2, uint a3,
                                         uint b0, uint b1) {
    asm volatile(
        "mma.sync.aligned.m16n8k8.row.col.f32.tf32.tf32.f32 "
        "{%0,%1,%2,%3}, {%4,%5,%6,%7}, {%8,%9}, {%0,%1,%2,%3};"
        : "+f"(d[0]), "+f"(d[1]), "+f"(d[2]), "+f"(d[3])
        : "r"(a0), "r"(a1), "r"(a2), "r"(a3), "r"(b0), "r"(b1));
}

// ---------------- init + CSR build ----------------
__global__ void k_init() {
    int i = blockIdx.x * blockDim.x + threadIdx.x;
    if (i < NN) g_deg[i] = 0;
    if (i < 3 * 2 * HH) ((float*)g_stats)[i] = 0.f;
}
__global__ void k_hist(const int* __restrict__ ei) {
    int e = blockIdx.x * blockDim.x + threadIdx.x;
    if (e < EE) atomicAdd(&g_deg[ei[EE + e]], 1);
}
__global__ void k_scan1() {
    __shared__ int s[1024];
    int t = threadIdx.x;
    int i = blockIdx.x * 1024 + t;
    int v = (i < NN) ? g_deg[i] : 0;
    s[t] = v;
    __syncthreads();
#pragma unroll
    for (int d = 1; d < 1024; d <<= 1) {
        int x = (t >= d) ? s[t - d] : 0;
        __syncthreads();
        s[t] += x;
        __syncthreads();
    }
    if (i < NN) g_off[i + 1] = s[t];
    if (t == 1023) g_bsum[blockIdx.x] = s[1023];
}
__global__ void k_scan2(int nb) {
    __shared__ int s[128];
    int t = threadIdx.x;
    int v = (t < nb) ? g_bsum[t] : 0;
    s[t] = v;
    __syncthreads();
#pragma unroll
    for (int d = 1; d < 128; d <<= 1) {
        int x = (t >= d) ? s[t - d] : 0;
        __syncthreads();
        s[t] += x;
        __syncthreads();
    }
    if (t < nb) g_bsum[t] = s[t] - v;
}
__global__ void k_scan3() {
    int i = blockIdx.x * blockDim.x + threadIdx.x;
    if (i < NN) {
        int tot = g_off[i + 1] + g_bsum[i >> 10];
        g_off[i + 1] = tot;
        int d = g_deg[i];
        g_deg[i] = tot - d;
        if (i == 0) g_off[0] = 0;
    }
}
__global__ void k_fill(const int* __restrict__ ei) {
    int e = blockIdx.x * blockDim.x + threadIdx.x;
    if (e < EE) {
        int d = ei[EE + e];
        int pos = atomicAdd(&g_deg[d], 1);
        g_csr[pos] = ei[e];
    }
}

// ---------------- layer-0 aggregation (20 cols) ----------------
__global__ void k_agg20(const float* __restrict__ x) {
    int w = (blockIdx.x * blockDim.x + threadIdx.x) >> 5;
    int lane = threadIdx.x & 31;
    if (w >= NN) return;
    int off = g_off[w], end = g_off[w + 1];
    float acc = 0.f;
    for (int j = off; j < end; j += 32) {
        int idx = (j + lane < end) ? g_csr[j + lane] : 0;
        int cnt = min(32, end - j);
        int t = 0;
        for (; t + 4 <= cnt; t += 4) {
            int s0 = __shfl_sync(0xffffffffu, idx, t);
            int s1 = __shfl_sync(0xffffffffu, idx, t + 1);
            int s2 = __shfl_sync(0xffffffffu, idx, t + 2);
            int s3 = __shfl_sync(0xffffffffu, idx, t + 3);
            if (lane < FIN) {
                float v0 = x[s0 * FIN + lane], v1 = x[s1 * FIN + lane];
                float v2 = x[s2 * FIN + lane], v3 = x[s3 * FIN + lane];
                acc += (v0 + v1) + (v2 + v3);
            }
        }
        for (; t < cnt; t++) {
            int s = __shfl_sync(0xffffffffu, idx, t);
            if (lane < FIN) acc += x[s * FIN + lane];
        }
    }
    if (lane < FIN) {
        int deg = end - off;
        g_a20[w * FIN + lane] = acc * (deg > 0 ? 1.f / (float)deg : 0.f);
    }
}

// ---------------- layer-0 GEMM (K=20) + bias + stats ----------------
__global__ __launch_bounds__(256) void k_gemm0(
    const float* __restrict__ x, const float* __restrict__ Wl,
    const float* __restrict__ bl, const float* __restrict__ Wr)
{
    __shared__ float Wls[FIN][HH], Wrs[FIN][HH], bls[HH];
    __shared__ float As[64][FIN + 1], Xs[64][FIN + 1];
    __shared__ float red[16][HH];
    int tid = threadIdx.x;
    for (int e = tid; e < HH * FIN; e += 256) {
        int o = e / FIN, k = e % FIN;
        Wls[k][o] = Wl[e];
        Wrs[k][o] = Wr[e];
    }
    if (tid < HH) bls[tid] = bl[tid];
    int n0 = blockIdx.x * 64;
    for (int e = tid; e < 64 * FIN; e += 256) {
        int i = e / FIN, k = e % FIN;
        int n = n0 + i;
        As[i][k] = (n < NN) ? g_a20[n * FIN + k] : 0.f;
        Xs[i][k] = (n < NN) ? x[n * FIN + k] : 0.f;
    }
    __syncthreads();
    int tm = tid >> 4, tn = tid & 15;
    ull acc[4][4];
#pragma unroll
    for (int r = 0; r < 4; r++)
#pragma unroll
        for (int c = 0; c < 4; c++)
            acc[r][c] = pk2(bls[tn * 8 + 2 * c], bls[tn * 8 + 2 * c + 1]);
#pragma unroll 4
    for (int k = 0; k < FIN; k++) {
        const ull* wl = (const ull*)&Wls[k][tn * 8];
        const ull* wr = (const ull*)&Wrs[k][tn * 8];
#pragma unroll
        for (int r = 0; r < 4; r++) {
            ull a2 = pk2(As[tm * 4 + r][k], As[tm * 4 + r][k]);
            ull x2 = pk2(Xs[tm * 4 + r][k], Xs[tm * 4 + r][k]);
#pragma unroll
            for (int c = 0; c < 4; c++) { fma2(acc[r][c], a2, wl[c]); fma2(acc[r][c], x2, wr[c]); }
        }
    }
    float av[4][8];
    float s[8] = {0,0,0,0,0,0,0,0}, s2[8] = {0,0,0,0,0,0,0,0};
#pragma unroll
    for (int r = 0; r < 4; r++) {
#pragma unroll
        for (int c = 0; c < 4; c++) upk2(acc[r][c], av[r][2 * c], av[r][2 * c + 1]);
        int n = n0 + tm * 4 + r;
        if (n < NN) {
            float4* o4 = (float4*)(g_pre + n * HH + tn * 8);
            o4[0] = make_float4(av[r][0], av[r][1], av[r][2], av[r][3]);
            o4[1] = make_float4(av[r][4], av[r][5], av[r][6], av[r][7]);
#pragma unroll
            for (int j = 0; j < 8; j++) { s[j] += av[r][j]; s2[j] += av[r][j] * av[r][j]; }
        }
    }
#pragma unroll
    for (int j = 0; j < 8; j++) red[tm][tn * 8 + j] = s[j];
    __syncthreads();
    if (tid < HH) {
        float t = 0.f;
#pragma unroll
        for (int w = 0; w < 16; w++) t += red[w][tid];
        atomicAdd(&g_stats[0][tid], t);
    }
    __syncthreads();
#pragma unroll
    for (int j = 0; j < 8; j++) red[tm][tn * 8 + j] = s2[j];
    __syncthreads();
    if (tid < HH) {
        float t = 0.f;
#pragma unroll
        for (int w = 0; w < 16; w++) t += red[w][tid];
        atomicAdd(&g_stats[0][HH + tid], t);
    }
}

// ---------------- GraphNorm finish ----------------
__global__ void k_finish(const float* __restrict__ gw, const float* __restrict__ gb,
                         const float* __restrict__ ga, int L) {
    int c = threadIdx.x;
    float invn = 1.f / (float)NN;
    float m  = g_stats[L][c] * invn;
    float e2 = g_stats[L][HH + c] * invn;
    float a = ga[c];
    float var = fmaxf(e2 - m * m * (2.f * a - a * a), 0.f);
    float scale = gw[c] * rsqrtf(var + EPSV);
    g_normP[L][c] = scale;
    g_normP[L][HH + c] = gb[c] - a * m * scale;
}

// ---------------- TF32 mma.sync dual GEMM: yl(fp16),yr = gelu(norm(pre)) @ {Wl,Wr}^T ----------------
#define OFF_WS   0
#define OFF_AS   (256 * 132 * 4)
#define OFF_NSC  (OFF_AS + 128 * 132 * 4)
#define OFF_NSH  (OFF_NSC + 512)
#define MMA_SMEM (OFF_NSH + 512)

__global__ __launch_bounds__(256) void k_gemm_mma(
    const float* __restrict__ Wl, const float* __restrict__ Wr, int Lm1)
{
    extern __shared__ char sm[];
    uint*  Ws  = (uint*)(sm + OFF_WS);
    uint*  As  = (uint*)(sm + OFF_AS);
    float* nsc = (float*)(sm + OFF_NSC);
    float* nsh = (float*)(sm + OFF_NSH);
    int tid = threadIdx.x;
    int wid = tid >> 5, lane = tid & 31;
    int tq = lane >> 2, tr = lane & 3;

    if (tid < HH) { nsc[tid] = g_normP[Lm1][tid]; nsh[tid] = g_normP[Lm1][HH + tid]; }

    // stage weights once: rows 0..127 = Wl, 128..255 = Wr (tf32)
    for (int e = tid; e < 256 * 32; e += 256) {
        int r = e >> 5, c4 = e & 31;
        const float4* src = (const float4*)((r < 128) ? Wl : Wr);
        float4 v = src[(r & 127) * 32 + c4];
        uint* d = Ws + r * 132 + c4 * 4;
        d[0] = cvt_tf32(v.x); d[1] = cvt_tf32(v.y);
        d[2] = cvt_tf32(v.z); d[3] = cvt_tf32(v.w);
    }

    const float4* P4 = (const float4*)g_pre;

    for (int tile = blockIdx.x; tile < NTILES; tile += gridDim.x) {
        int m0 = tile * 128;
        __syncthreads();
        // stage A tile: norm + gelu + tf32
        for (int e = tid; e < 128 * 32; e += 256) {
            int r = e >> 5, c4 = e & 31;
            int row = m0 + r;
            float4 v = make_float4(0.f, 0.f, 0.f, 0.f);
            if (row < NN) v = P4[row * 32 + c4];
            int c = c4 * 4;
            uint* d = As + r * 132 + c;
            d[0] = cvt_tf32(gelu_f(v.x * nsc[c + 0] + nsh[c + 0]));
            d[1] = cvt_tf32(gelu_f(v.y * nsc[c + 1] + nsh[c + 1]));
            d[2] = cvt_tf32(gelu_f(v.z * nsc[c + 2] + nsh[c + 2]));
            d[3] = cvt_tf32(gelu_f(v.w * nsc[c + 3] + nsh[c + 3]));
        }
        __syncthreads();

        int mrow = wid * 16 + tq;
        const uint* Arow0 = As + mrow * 132;
        const uint* Arow1 = As + (mrow + 8) * 132;
#pragma unroll 1
        for (int chunk = 0; chunk < 4; chunk++) {
            float dfr[8][4];
#pragma unroll
            for (int j = 0; j < 8; j++)
#pragma unroll
                for (int c = 0; c < 4; c++) dfr[j][c] = 0.f;
#pragma unroll
            for (int k8 = 0; k8 < 16; k8++) {
                int kk = k8 * 8;
                uint a0 = Arow0[kk + tr];
                uint a1 = Arow1[kk + tr];
                uint a2 = Arow0[kk + 4 + tr];
                uint a3 = Arow1[kk + 4 + tr];
                const uint* wb = Ws + (chunk * 64 + tq) * 132 + kk + tr;
#pragma unroll
                for (int j = 0; j < 8; j++) {
                    uint b0 = wb[j * 8 * 132];
                    uint b1 = wb[j * 8 * 132 + 4];
                    mma_tf32(dfr[j], a0, a1, a2, a3, b0, b1);
                }
            }
            int row0 = m0 + mrow;
#pragma unroll
            for (int j = 0; j < 8; j++) {
                int gcol = chunk * 64 + j * 8 + tr * 2;
                if (gcol < HH) {
                    // yl: fp16 packed
                    if (row0 < NN)
                        g_yl16[row0 * 64 + (gcol >> 1)] = pack_h2(dfr[j][0], dfr[j][1]);
                    if (row0 + 8 < NN)
                        g_yl16[(row0 + 8) * 64 + (gcol >> 1)] = pack_h2(dfr[j][2], dfr[j][3]);
                } else {
                    int col = gcol - HH;
                    if (row0 < NN)
                        *(float2*)(g_yr + row0 * HH + col) = make_float2(dfr[j][0], dfr[j][1]);
                    if (row0 + 8 < NN)
                        *(float2*)(g_yr + (row0 + 8) * HH + col) = make_float2(dfr[j][2], dfr[j][3]);
                }
            }
        }
    }
}

// ---------------- aggregation of yl(fp16) + add yr + bias + stats ----------------
__global__ __launch_bounds__(256) void k_aggstats(const float* __restrict__ bl, int L)
{
    __shared__ float red[8][HH];
    int tid = threadIdx.x;
    int lane = tid & 31, wp = tid >> 5;
    const uint2* yl2 = (const uint2*)g_yl16;     // 4 halves per lane -> ch lane*4..+3
    const float4* yr4 = (const float4*)g_yr;
    float4 bias = ((const float4*)bl)[lane];
    float s[4] = {0, 0, 0, 0}, s2[4] = {0, 0, 0, 0};
    int gw = blockIdx.x * 8 + wp;
    const int stride = gridDim.x * 8;
    for (int w = gw; w < NN; w += stride) {
        int off = g_off[w], end = g_off[w + 1];
        float4 acc = make_float4(0.f, 0.f, 0.f, 0.f);
        for (int j = off; j < end; j += 32) {
            int idx = (j + lane < end) ? g_csr[j + lane] : 0;
            int cnt = min(32, end - j);
            int t = 0;
            for (; t + 4 <= cnt; t += 4) {
                int s0 = __shfl_sync(0xffffffffu, idx, t);
                int s1 = __shfl_sync(0xffffffffu, idx, t + 1);
                int s2i = __shfl_sync(0xffffffffu, idx, t + 2);
                int s3 = __shfl_sync(0xffffffffu, idx, t + 3);
                uint2 u0 = yl2[s0 * 32 + lane];
                uint2 u1 = yl2[s1 * 32 + lane];
                uint2 u2 = yl2[s2i * 32 + lane];
                uint2 u3 = yl2[s3 * 32 + lane];
                float2 a0 = __half22float2(*(const __half2*)&u0.x);
                float2 b0 = __half22float2(*(const __half2*)&u0.y);
                float2 a1 = __half22float2(*(const __half2*)&u1.x);
                float2 b1 = __half22float2(*(const __half2*)&u1.y);
                float2 a2 = __half22float2(*(const __half2*)&u2.x);
                float2 b2 = __half22float2(*(const __half2*)&u2.y);
                float2 a3 = __half22float2(*(const __half2*)&u3.x);
                float2 b3 = __half22float2(*(const __half2*)&u3.y);
                acc.x += (a0.x + a1.x) + (a2.x + a3.x);
                acc.y += (a0.y + a1.y) + (a2.y + a3.y);
                acc.z += (b0.x + b1.x) + (b2.x + b3.x);
                acc.w += (b0.y + b1.y) + (b2.y + b3.y);
            }
            for (; t < cnt; t++) {
                int sx = __shfl_sync(0xffffffffu, idx, t);
                uint2 u = yl2[sx * 32 + lane];
                float2 a = __half22float2(*(const __half2*)&u.x);
                float2 b = __half22float2(*(const __half2*)&u.y);
                acc.x += a.x; acc.y += a.y; acc.z += b.x; acc.w += b.y;
            }
        }
        int deg = end - off;
        float inv = (deg > 0) ? 1.f / (float)deg : 0.f;
        float4 r = yr4[w * 32 + lane];
        r.x = acc.x * inv + r.x + bias.x;
        r.y = acc.y * inv + r.y + bias.y;
        r.z = acc.z * inv + r.z + bias.z;
        r.w = acc.w * inv + r.w + bias.w;
        ((float4*)g_pre)[w * 32 + lane] = r;
        s[0] += r.x; s2[0] += r.x * r.x;
        s[1] += r.y; s2[1] += r.y * r.y;
        s[2] += r.z; s2[2] += r.z * r.z;
        s[3] += r.w; s2[3] += r.w * r.w;
    }
#pragma unroll
    for (int i = 0; i < 4; i++) red[wp][lane * 4 + i] = s[i];
    __syncthreads();
    if (tid < HH) {
        float t = 0.f;
#pragma unroll
        for (int w = 0; w < 8; w++) t += red[w][tid];
        atomicAdd(&g_stats[L][tid], t);
    }
    __syncthreads();
#pragma unroll
    for (int i = 0; i < 4; i++) red[wp][lane * 4 + i] = s2[i];
    __syncthreads();
    if (tid < HH) {
        float t = 0.f;
#pragma unroll
        for (int w = 0; w < 8; w++) t += red[w][tid];
        atomicAdd(&g_stats[L][HH + tid], t);
    }
}

// ---------------- fused MLP head with norm+gelu on input ----------------
__global__ __launch_bounds__(128) void k_mlp(
    const float* __restrict__ hW1, const float* __restrict__ hb1,
    const float* __restrict__ hW2, const float* __restrict__ hb2,
    const float* __restrict__ hW3, const float* __restrict__ hb3,
    float* __restrict__ out)
{
    extern __shared__ float smf[];
    float* W1t = smf;                // [128][64]
    float* W2t = W1t + 128 * 64;     // [64][32]
    float* w3  = W2t + 64 * 32;      // [32]
    float* b1  = w3 + 32;            // [64]
    float* b2  = b1 + 64;            // [32]
    float* nsc = b2 + 32;            // [128]
    float* nsh = nsc + 128;          // [128]
    float* hs  = nsh + 128;          // [128][129]

    int tid = threadIdx.x;
    for (int e = tid; e < 8192; e += 128) { int o = e >> 7, k = e & 127; W1t[k * 64 + o] = hW1[e]; }
    for (int e = tid; e < 2048; e += 128) { int o = e >> 6, k = e & 63;  W2t[k * 32 + o] = hW2[e]; }
    if (tid < 32) w3[tid] = hW3[tid];
    if (tid < 64) b1[tid] = hb1[tid];
    if (tid < 32) b2[tid] = hb2[tid];
    nsc[tid] = g_normP[2][tid];
    nsh[tid] = g_normP[2][HH + tid];
    __syncthreads();

    int n0 = blockIdx.x * 128;
    const float4* p4 = (const float4*)g_pre;
    for (int e = tid; e < 128 * 32; e += 128) {
        int r = e >> 5, cc = e & 31;
        int n = n0 + r;
        float4 v = make_float4(0.f, 0.f, 0.f, 0.f);
        if (n < NN) v = p4[n * 32 + cc];
        int c = cc * 4;
        hs[(c + 0) * 129 + r] = gelu_f(v.x * nsc[c + 0] + nsh[c + 0]);
        hs[(c + 1) * 129 + r] = gelu_f(v.y * nsc[c + 1] + nsh[c + 1]);
        hs[(c + 2) * 129 + r] = gelu_f(v.z * nsc[c + 2] + nsh[c + 2]);
        hs[(c + 3) * 129 + r] = gelu_f(v.w * nsc[c + 3] + nsh[c + 3]);
    }
    __syncthreads();

    int n = n0 + tid;
    if (n >= NN) return;

    ull acc1[32];
#pragma unroll
    for (int i = 0; i < 32; i++) acc1[i] = pk2(b1[2 * i], b1[2 * i + 1]);
    for (int k = 0; k < 128; k++) {
        float hv = hs[k * 129 + tid];
        ull a2 = pk2(hv, hv);
        const ull* wr = (const ull*)(W1t + k * 64);
#pragma unroll
        for (int i = 0; i < 32; i++) fma2(acc1[i], a2, wr[i]);
    }
    float y1[64];
#pragma unroll
    for (int i = 0; i < 32; i++) {
        float lo, hi;
        upk2(acc1[i], lo, hi);
        y1[2 * i] = gelu_f(lo);
        y1[2 * i + 1] = gelu_f(hi);
    }
    ull acc2[16];
#pragma unroll
    for (int i = 0; i < 16; i++) acc2[i] = pk2(b2[2 * i], b2[2 * i + 1]);
#pragma unroll 4
    for (int k = 0; k < 64; k++) {
        ull a2 = pk2(y1[k], y1[k]);
        const ull* wr = (const ull*)(W2t + k * 32);
#pragma unroll
        for (int i = 0; i < 16; i++) fma2(acc2[i], a2, wr[i]);
    }
    float s = 0.f;
#pragma unroll
    for (int i = 0; i < 16; i++) {
        float lo, hi;
        upk2(acc2[i], lo, hi);
        s += gelu_f(lo) * w3[2 * i] + gelu_f(hi) * w3[2 * i + 1];
    }
    s += hb3[0];
    out[n] = 1.f / (1.f + expf(-s));
}

// ---------------- launch ----------------
extern "C" void kernel_launch(void* const* d_in, const int* in_sizes, int n_in,
                              void* d_out, int out_size)
{
    const float* x   = (const float*)d_in[0];
    const int*   ei  = (const int*)d_in[1];
    const float* Wl[3] = {(const float*)d_in[2],  (const float*)d_in[8],  (const float*)d_in[14]};
    const float* bl[3] = {(const float*)d_in[3],  (const float*)d_in[9],  (const float*)d_in[15]};
    const float* Wr[3] = {(const float*)d_in[4],  (const float*)d_in[10], (const float*)d_in[16]};
    const float* gw[3] = {(const float*)d_in[5],  (const float*)d_in[11], (const float*)d_in[17]};
    const float* gb[3] = {(const float*)d_in[6],  (const float*)d_in[12], (const float*)d_in[18]};
    const float* ga[3] = {(const float*)d_in[7],  (const float*)d_in[13], (const float*)d_in[19]};
    const float* hW1 = (const float*)d_in[20];
    const float* hb1 = (const float*)d_in[21];
    const float* hW2 = (const float*)d_in[22];
    const float* hb2 = (const float*)d_in[23];
    const float* hW3 = (const float*)d_in[24];
    const float* hb3 = (const float*)d_in[25];
    float* out = (float*)d_out;

    const int SCAN_BLOCKS = (NN + 1023) / 1024;      // 98
    const int MLP_SMEM = (8192 + 2048 + 32 + 64 + 32 + 256 + 128 * 129) * 4;
    cudaFuncSetAttribute(k_mlp, cudaFuncAttributeMaxDynamicSharedMemorySize, MLP_SMEM);
    cudaFuncSetAttribute(k_gemm_mma, cudaFuncAttributeMaxDynamicSharedMemorySize, MMA_SMEM);

    // CSR build
    k_init<<<(NN + 255) / 256, 256>>>();
    k_hist<<<(EE + 255) / 256, 256>>>(ei);
    k_scan1<<<SCAN_BLOCKS, 1024>>>();
    k_scan2<<<1, 128>>>(SCAN_BLOCKS);
    k_scan3<<<(NN + 255) / 256, 256>>>();
    k_fill<<<(EE + 255) / 256, 256>>>(ei);

    // layer 0
    k_agg20<<<(NN * 32 + 255) / 256, 256>>>(x);
    k_gemm0<<<(NN + 63) / 64, 256>>>(x, Wl[0], bl[0], Wr[0]);
    k_finish<<<1, 128>>>(gw[0], gb[0], ga[0], 0);

    // layers 1, 2
    for (int L = 1; L <= 2; L++) {
        k_gemm_mma<<<148, 256, MMA_SMEM>>>(Wl[L], Wr[L], L - 1);
        k_aggstats<<<782, 256>>>(bl[L], L);
        k_finish<<<1, 128>>>(gw[L], gb[L], ga[L], L);
    }

    // MLP head
    k_mlp<<<(NN + 127) / 128, 128, MLP_SMEM>>>(hW1, hb1, hW2, hb2, hW3, hb3, out);
}

// round 6
// speedup vs baseline: 1.6718x; 1.0712x over previous
#include <cuda_runtime.h>
#include <cuda_fp16.h>
#include <math.h>

#define NN   100000
#define EE   1600000
#define FIN  20
#define HH   128
#define EPSV 1e-5f
#define NTILES 782            // ceil(NN/128)

// ---------------- scratch ----------------
__device__ __align__(16) unsigned int g_yl16[NN * 64];   // fp16x2: [N][64] half2 = 128 ch
__device__ __align__(16) float g_yr[NN * HH];
__device__ __align__(16) float g_pre[NN * HH];
__device__ __align__(16) float g_a20[NN * FIN];
__device__ int   g_deg[NN];
__device__ int   g_off[NN + 1];
__device__ int   g_csr[EE];
__device__ int   g_bsum[128];
__device__ float g_stats[3][2 * HH];

typedef unsigned long long ull;
typedef unsigned int uint;

__device__ __forceinline__ ull pk2(float lo, float hi) {
    ull r; asm("mov.b64 %0, {%1,%2};" : "=l"(r) : "f"(lo), "f"(hi)); return r;
}
__device__ __forceinline__ void upk2(ull v, float& lo, float& hi) {
    asm("mov.b64 {%0,%1}, %2;" : "=f"(lo), "=f"(hi) : "l"(v));
}
__device__ __forceinline__ void fma2(ull& d, ull a, ull b) {
    asm("fma.rn.f32x2 %0, %1, %2, %0;" : "+l"(d) : "l"(a), "l"(b));
}
__device__ __forceinline__ float gelu_f(float x) {
    return 0.5f * x * (1.0f + erff(x * 0.70710678118654752f));
}
__device__ __forceinline__ uint cvt_tf32(float v) {
    uint r; asm("cvt.rna.tf32.f32 %0, %1;" : "=r"(r) : "f"(v)); return r;
}
__device__ __forceinline__ uint pack_h2(float lo, float hi) {
    uint r; asm("cvt.rn.f16x2.f32 %0, %2, %1;" : "=r"(r) : "f"(lo), "f"(hi)); return r;
}
__device__ __forceinline__ void mma_tf32(float* d, uint a0, uint a1, uint a2, uint a3,
                                         uint b0, uint b1) {
    asm volatile(
        "mma.sync.aligned.m16n8k8.row.col.f32.tf32.tf32.f32 "
        "{%0,%1,%2,%3}, {%4,%5,%6,%7}, {%8,%9}, {%0,%1,%2,%3};"
        : "+f"(d[0]), "+f"(d[1]), "+f"(d[2]), "+f"(d[3])
        : "r"(a0), "r"(a1), "r"(a2), "r"(a3), "r"(b0), "r"(b1));
}

// ---------------- init + CSR build ----------------
__global__ void k_init() {
    int i = blockIdx.x * blockDim.x + threadIdx.x;
    if (i < NN) g_deg[i] = 0;
    if (i < 3 * 2 * HH) ((float*)g_stats)[i] = 0.f;
}
__global__ void k_hist(const int* __restrict__ ei) {
    int e = blockIdx.x * blockDim.x + threadIdx.x;
    if (e < EE) atomicAdd(&g_deg[ei[EE + e]], 1);
}
__global__ void k_scan1() {
    __shared__ int s[1024];
    int t = threadIdx.x;
    int i = blockIdx.x * 1024 + t;
    int v = (i < NN) ? g_deg[i] : 0;
    s[t] = v;
    __syncthreads();
#pragma unroll
    for (int d = 1; d < 1024; d <<= 1) {
        int x = (t >= d) ? s[t - d] : 0;
        __syncthreads();
        s[t] += x;
        __syncthreads();
    }
    if (i < NN) g_off[i + 1] = s[t];
    if (t == 1023) g_bsum[blockIdx.x] = s[1023];
}
__global__ void k_scan2(int nb) {
    __shared__ int s[128];
    int t = threadIdx.x;
    int v = (t < nb) ? g_bsum[t] : 0;
    s[t] = v;
    __syncthreads();
#pragma unroll
    for (int d = 1; d < 128; d <<= 1) {
        int x = (t >= d) ? s[t - d] : 0;
        __syncthreads();
        s[t] += x;
        __syncthreads();
    }
    if (t < nb) g_bsum[t] = s[t] - v;
}
__global__ void k_scan3() {
    int i = blockIdx.x * blockDim.x + threadIdx.x;
    if (i < NN) {
        int tot = g_off[i + 1] + g_bsum[i >> 10];
        g_off[i + 1] = tot;
        int d = g_deg[i];
        g_deg[i] = tot - d;
        if (i == 0) g_off[0] = 0;
    }
}
__global__ void k_fill(const int* __restrict__ ei) {
    int e = blockIdx.x * blockDim.x + threadIdx.x;
    if (e < EE) {
        int d = ei[EE + e];
        int pos = atomicAdd(&g_deg[d], 1);
        g_csr[pos] = ei[e];
    }
}

// ---------------- layer-0 aggregation (20 cols) ----------------
__global__ void k_agg20(const float* __restrict__ x) {
    int w = (blockIdx.x * blockDim.x + threadIdx.x) >> 5;
    int lane = threadIdx.x & 31;
    if (w >= NN) return;
    int off = g_off[w], end = g_off[w + 1];
    float acc = 0.f;
    for (int j = off; j < end; j += 32) {
        int idx = (j + lane < end) ? g_csr[j + lane] : 0;
        int cnt = min(32, end - j);
        int t = 0;
        for (; t + 4 <= cnt; t += 4) {
            int s0 = __shfl_sync(0xffffffffu, idx, t);
            int s1 = __shfl_sync(0xffffffffu, idx, t + 1);
            int s2 = __shfl_sync(0xffffffffu, idx, t + 2);
            int s3 = __shfl_sync(0xffffffffu, idx, t + 3);
            if (lane < FIN) {
                float v0 = x[s0 * FIN + lane], v1 = x[s1 * FIN + lane];
                float v2 = x[s2 * FIN + lane], v3 = x[s3 * FIN + lane];
                acc += (v0 + v1) + (v2 + v3);
            }
        }
        for (; t < cnt; t++) {
            int s = __shfl_sync(0xffffffffu, idx, t);
            if (lane < FIN) acc += x[s * FIN + lane];
        }
    }
    if (lane < FIN) {
        int deg = end - off;
        g_a20[w * FIN + lane] = acc * (deg > 0 ? 1.f / (float)deg : 0.f);
    }
}

// ---------------- layer-0 GEMM (K=20) + bias + stats ----------------
__global__ __launch_bounds__(256) void k_gemm0(
    const float* __restrict__ x, const float* __restrict__ Wl,
    const float* __restrict__ bl, const float* __restrict__ Wr)
{
    __shared__ float Wls[FIN][HH], Wrs[FIN][HH], bls[HH];
    __shared__ float As[64][FIN + 1], Xs[64][FIN + 1];
    __shared__ float red[16][HH];
    int tid = threadIdx.x;
    for (int e = tid; e < HH * FIN; e += 256) {
        int o = e / FIN, k = e % FIN;
        Wls[k][o] = Wl[e];
        Wrs[k][o] = Wr[e];
    }
    if (tid < HH) bls[tid] = bl[tid];
    int n0 = blockIdx.x * 64;
    for (int e = tid; e < 64 * FIN; e += 256) {
        int i = e / FIN, k = e % FIN;
        int n = n0 + i;
        As[i][k] = (n < NN) ? g_a20[n * FIN + k] : 0.f;
        Xs[i][k] = (n < NN) ? x[n * FIN + k] : 0.f;
    }
    __syncthreads();
    int tm = tid >> 4, tn = tid & 15;
    ull acc[4][4];
#pragma unroll
    for (int r = 0; r < 4; r++)
#pragma unroll
        for (int c = 0; c < 4; c++)
            acc[r][c] = pk2(bls[tn * 8 + 2 * c], bls[tn * 8 + 2 * c + 1]);
#pragma unroll 4
    for (int k = 0; k < FIN; k++) {
        const ull* wl = (const ull*)&Wls[k][tn * 8];
        const ull* wr = (const ull*)&Wrs[k][tn * 8];
#pragma unroll
        for (int r = 0; r < 4; r++) {
            ull a2 = pk2(As[tm * 4 + r][k], As[tm * 4 + r][k]);
            ull x2 = pk2(Xs[tm * 4 + r][k], Xs[tm * 4 + r][k]);
#pragma unroll
            for (int c = 0; c < 4; c++) { fma2(acc[r][c], a2, wl[c]); fma2(acc[r][c], x2, wr[c]); }
        }
    }
    float av[4][8];
    float s[8] = {0,0,0,0,0,0,0,0}, s2[8] = {0,0,0,0,0,0,0,0};
#pragma unroll
    for (int r = 0; r < 4; r++) {
#pragma unroll
        for (int c = 0; c < 4; c++) upk2(acc[r][c], av[r][2 * c], av[r][2 * c + 1]);
        int n = n0 + tm * 4 + r;
        if (n < NN) {
            float4* o4 = (float4*)(g_pre + n * HH + tn * 8);
            o4[0] = make_float4(av[r][0], av[r][1], av[r][2], av[r][3]);
            o4[1] = make_float4(av[r][4], av[r][5], av[r][6], av[r][7]);
#pragma unroll
            for (int j = 0; j < 8; j++) { s[j] += av[r][j]; s2[j] += av[r][j] * av[r][j]; }
        }
    }
#pragma unroll
    for (int j = 0; j < 8; j++) red[tm][tn * 8 + j] = s[j];
    __syncthreads();
    if (tid < HH) {
        float t = 0.f;
#pragma unroll
        for (int w = 0; w < 16; w++) t += red[w][tid];
        atomicAdd(&g_stats[0][tid], t);
    }
    __syncthreads();
#pragma unroll
    for (int j = 0; j < 8; j++) red[tm][tn * 8 + j] = s2[j];
    __syncthreads();
    if (tid < HH) {
        float t = 0.f;
#pragma unroll
        for (int w = 0; w < 16; w++) t += red[w][tid];
        atomicAdd(&g_stats[0][HH + tid], t);
    }
}

// ---------------- TF32 mma.sync dual GEMM (fragment-order smem layouts) ----------------
// Bf: [cg(2)][k8(16)][jp(8)][lane(32) x uint4]   (j0b0,j0b1,j1b0,j1b1)  128KB
// Af: [rt(8)][k8(16)] rows of 132 uints, lane uint4 = (a0,a1,a2,a3)     67.6KB
#define BF_UINTS (2 * 16 * 8 * 128)
#define AF_UINTS (8 * 16 * 132)
#define OFF_BF   0
#define OFF_AF   (BF_UINTS * 4)
#define OFF_NSC  (OFF_AF + AF_UINTS * 4)
#define OFF_NSH  (OFF_NSC + 512)
#define MMA_SMEM (OFF_NSH + 512)

__global__ __launch_bounds__(256, 1) void k_gemm_mma(
    const float* __restrict__ Wl, const float* __restrict__ Wr,
    const float* __restrict__ gw, const float* __restrict__ gb,
    const float* __restrict__ ga, int Lm1)
{
    extern __shared__ char sm[];
    uint*  Bf  = (uint*)(sm + OFF_BF);
    uint*  Af  = (uint*)(sm + OFF_AF);
    float* nsc = (float*)(sm + OFF_NSC);
    float* nsh = (float*)(sm + OFF_NSH);
    int tid = threadIdx.x;
    int wid = tid >> 5, lane = tid & 31;
    int tq = lane >> 2, tr = lane & 3;
    int rg = wid & 3, cg = wid >> 2;

    // fused GraphNorm finish
    if (tid < HH) {
        float invn = 1.f / (float)NN;
        float m  = g_stats[Lm1][tid] * invn;
        float e2 = g_stats[Lm1][HH + tid] * invn;
        float a = ga[tid];
        float var = fmaxf(e2 - m * m * (2.f * a - a * a), 0.f);
        float scale = gw[tid] * rsqrtf(var + EPSV);
        nsc[tid] = scale;
        nsh[tid] = gb[tid] - a * m * scale;
    }

    // stage B fragments once: cols 0..127 = Wl rows, 128..255 = Wr rows
    for (int e = tid; e < 256 * 32; e += 256) {
        int c = e >> 5, c4 = e & 31;
        const float4* src = (const float4*)((c < 128) ? Wl : Wr);
        float4 v = src[(c & 127) * 32 + c4];
        int k8 = c4 >> 1, kh = c4 & 1;
        int cgi = c >> 7, j = (c >> 3) & 15, jp = j >> 1, jl = j & 1, nq = c & 7;
        uint* dst = Bf + (((cgi * 16 + k8) * 8 + jp) << 7) + jl * 2 + kh;
        dst[(nq * 4 + 0) * 4] = cvt_tf32(v.x);
        dst[(nq * 4 + 1) * 4] = cvt_tf32(v.y);
        dst[(nq * 4 + 2) * 4] = cvt_tf32(v.z);
        dst[(nq * 4 + 3) * 4] = cvt_tf32(v.w);
    }

    const float4* P4 = (const float4*)g_pre;

    for (int tile = blockIdx.x; tile < NTILES; tile += gridDim.x) {
        int m0 = tile * 128;
        __syncthreads();   // prior tile's fragment reads done
        // stage A tile in fragment order (norm + gelu + tf32 fused)
        for (int e = tid; e < 128 * 32; e += 256) {
            int r = e >> 5, c4 = e & 31;
            int row = m0 + r;
            float4 v = make_float4(0.f, 0.f, 0.f, 0.f);
            if (row < NN) v = P4[row * 32 + c4];
            int c = c4 * 4;
            float g0 = gelu_f(v.x * nsc[c + 0] + nsh[c + 0]);
            float g1 = gelu_f(v.y * nsc[c + 1] + nsh[c + 1]);
            float g2 = gelu_f(v.z * nsc[c + 2] + nsh[c + 2]);
            float g3 = gelu_f(v.w * nsc[c + 3] + nsh[c + 3]);
            int rt = r >> 4, rr = r & 15, rh = rr >> 3, tq_ = rr & 7;
            int k8 = c4 >> 1, kh = c4 & 1;
            uint* dst = Af + (rt * 16 + k8) * 132 + kh * 2 + rh;
            dst[(tq_ * 4 + 0) * 4] = cvt_tf32(g0);
            dst[(tq_ * 4 + 1) * 4] = cvt_tf32(g1);
            dst[(tq_ * 4 + 2) * 4] = cvt_tf32(g2);
            dst[(tq_ * 4 + 3) * 4] = cvt_tf32(g3);
        }
        __syncthreads();

        int rt0 = rg * 2, rt1 = rg * 2 + 1;
        float acc[2][16][4];
#pragma unroll
        for (int t2 = 0; t2 < 2; t2++)
#pragma unroll
            for (int j = 0; j < 16; j++)
#pragma unroll
                for (int c = 0; c < 4; c++) acc[t2][j][c] = 0.f;

#pragma unroll 4
        for (int k8 = 0; k8 < 16; k8++) {
            uint4 A0 = ((const uint4*)(Af + (rt0 * 16 + k8) * 132))[lane];
            uint4 A1 = ((const uint4*)(Af + (rt1 * 16 + k8) * 132))[lane];
            const uint4* Bp = (const uint4*)(Bf + (((cg * 16 + k8) * 8) << 7));
#pragma unroll
            for (int jp = 0; jp < 8; jp++) {
                uint4 B = Bp[(jp << 5) + lane];
                mma_tf32(acc[0][jp * 2],     A0.x, A0.y, A0.z, A0.w, B.x, B.y);
                mma_tf32(acc[1][jp * 2],     A1.x, A1.y, A1.z, A1.w, B.x, B.y);
                mma_tf32(acc[0][jp * 2 + 1], A0.x, A0.y, A0.z, A0.w, B.z, B.w);
                mma_tf32(acc[1][jp * 2 + 1], A1.x, A1.y, A1.z, A1.w, B.z, B.w);
            }
        }

        // epilogue: warp covers rows rg*32..+32, cols cg*128..+128
#pragma unroll
        for (int t2 = 0; t2 < 2; t2++) {
            int row0 = m0 + rg * 32 + t2 * 16 + tq;
            if (cg == 0) {
#pragma unroll
                for (int j = 0; j < 16; j++) {
                    int hidx = j * 4 + tr;     // half2 index (cols j*8+tr*2, +1)
                    if (row0 < NN)
                        g_yl16[row0 * 64 + hidx] = pack_h2(acc[t2][j][0], acc[t2][j][1]);
                    if (row0 + 8 < NN)
                        g_yl16[(row0 + 8) * 64 + hidx] = pack_h2(acc[t2][j][2], acc[t2][j][3]);
                }
            } else {
#pragma unroll
                for (int j = 0; j < 16; j++) {
                    int col = j * 8 + tr * 2;
                    if (row0 < NN)
                        *(float2*)(g_yr + row0 * HH + col) = make_float2(acc[t2][j][0], acc[t2][j][1]);
                    if (row0 + 8 < NN)
                        *(float2*)(g_yr + (row0 + 8) * HH + col) = make_float2(acc[t2][j][2], acc[t2][j][3]);
                }
            }
        }
    }
}

// ---------------- aggregation of yl(fp16) + add yr + bias + stats ----------------
__global__ __launch_bounds__(256) void k_aggstats(const float* __restrict__ bl, int L)
{
    __shared__ float red[8][HH];
    int tid = threadIdx.x;
    int lane = tid & 31, wp = tid >> 5;
    const uint2* yl2 = (const uint2*)g_yl16;
    const float4* yr4 = (const float4*)g_yr;
    float4 bias = ((const float4*)bl)[lane];
    float s[4] = {0, 0, 0, 0}, s2[4] = {0, 0, 0, 0};
    int gw = blockIdx.x * 8 + wp;
    const int stride = gridDim.x * 8;
    for (int w = gw; w < NN; w += stride) {
        int off = g_off[w], end = g_off[w + 1];
        float4 acc = make_float4(0.f, 0.f, 0.f, 0.f);
        for (int j = off; j < end; j += 32) {
            int idx = (j + lane < end) ? g_csr[j + lane] : 0;
            int cnt = min(32, end - j);
            int t = 0;
            for (; t + 4 <= cnt; t += 4) {
                int s0 = __shfl_sync(0xffffffffu, idx, t);
                int s1 = __shfl_sync(0xffffffffu, idx, t + 1);
                int s2i = __shfl_sync(0xffffffffu, idx, t + 2);
                int s3 = __shfl_sync(0xffffffffu, idx, t + 3);
                uint2 u0 = yl2[s0 * 32 + lane];
                uint2 u1 = yl2[s1 * 32 + lane];
                uint2 u2 = yl2[s2i * 32 + lane];
                uint2 u3 = yl2[s3 * 32 + lane];
                float2 a0 = __half22float2(*(const __half2*)&u0.x);
                float2 b0 = __half22float2(*(const __half2*)&u0.y);
                float2 a1 = __half22float2(*(const __half2*)&u1.x);
                float2 b1 = __half22float2(*(const __half2*)&u1.y);
                float2 a2 = __half22float2(*(const __half2*)&u2.x);
                float2 b2 = __half22float2(*(const __half2*)&u2.y);
                float2 a3 = __half22float2(*(const __half2*)&u3.x);
                float2 b3 = __half22float2(*(const __half2*)&u3.y);
                acc.x += (a0.x + a1.x) + (a2.x + a3.x);
                acc.y += (a0.y + a1.y) + (a2.y + a3.y);
                acc.z += (b0.x + b1.x) + (b2.x + b3.x);
                acc.w += (b0.y + b1.y) + (b2.y + b3.y);
            }
            for (; t < cnt; t++) {
                int sx = __shfl_sync(0xffffffffu, idx, t);
                uint2 u = yl2[sx * 32 + lane];
                float2 a = __half22float2(*(const __half2*)&u.x);
                float2 b = __half22float2(*(const __half2*)&u.y);
                acc.x += a.x; acc.y += a.y; acc.z += b.x; acc.w += b.y;
            }
        }
        int deg = end - off;
        float inv = (deg > 0) ? 1.f / (float)deg : 0.f;
        float4 r = yr4[w * 32 + lane];
        r.x = acc.x * inv + r.x + bias.x;
        r.y = acc.y * inv + r.y + bias.y;
        r.z = acc.z * inv + r.z + bias.z;
        r.w = acc.w * inv + r.w + bias.w;
        ((float4*)g_pre)[w * 32 + lane] = r;
        s[0] += r.x; s2[0] += r.x * r.x;
        s[1] += r.y; s2[1] += r.y * r.y;
        s[2] += r.z; s2[2] += r.z * r.z;
        s[3] += r.w; s2[3] += r.w * r.w;
    }
#pragma unroll
    for (int i = 0; i < 4; i++) red[wp][lane * 4 + i] = s[i];
    __syncthreads();
    if (tid < HH) {
        float t = 0.f;
#pragma unroll
        for (int w = 0; w < 8; w++) t += red[w][tid];
        atomicAdd(&g_stats[L][tid], t);
    }
    __syncthreads();
#pragma unroll
    for (int i = 0; i < 4; i++) red[wp][lane * 4 + i] = s2[i];
    __syncthreads();
    if (tid < HH) {
        float t = 0.f;
#pragma unroll
        for (int w = 0; w < 8; w++) t += red[w][tid];
        atomicAdd(&g_stats[L][HH + tid], t);
    }
}

// ---------------- fused MLP head with norm+gelu on input (finish fused) ----------------
__global__ __launch_bounds__(128) void k_mlp(
    const float* __restrict__ hW1, const float* __restrict__ hb1,
    const float* __restrict__ hW2, const float* __restrict__ hb2,
    const float* __restrict__ hW3, const float* __restrict__ hb3,
    const float* __restrict__ gw2, const float* __restrict__ gb2,
    const float* __restrict__ ga2,
    float* __restrict__ out)
{
    extern __shared__ float smf[];
    float* W1t = smf;                // [128][64]
    float* W2t = W1t + 128 * 64;     // [64][32]
    float* w3  = W2t + 64 * 32;      // [32]
    float* b1  = w3 + 32;            // [64]
    float* b2  = b1 + 64;            // [32]
    float* nsc = b2 + 32;            // [128]
    float* nsh = nsc + 128;          // [128]
    float* hs  = nsh + 128;          // [128][129]

    int tid = threadIdx.x;
    for (int e = tid; e < 8192; e += 128) { int o = e >> 7, k = e & 127; W1t[k * 64 + o] = hW1[e]; }
    for (int e = tid; e < 2048; e += 128) { int o = e >> 6, k = e & 63;  W2t[k * 32 + o] = hW2[e]; }
    if (tid < 32) w3[tid] = hW3[tid];
    if (tid < 64) b1[tid] = hb1[tid];
    if (tid < 32) b2[tid] = hb2[tid];
    {
        float invn = 1.f / (float)NN;
        float m  = g_stats[2][tid] * invn;
        float e2 = g_stats[2][HH + tid] * invn;
        float a = ga2[tid];
        float var = fmaxf(e2 - m * m * (2.f * a - a * a), 0.f);
        float scale = gw2[tid] * rsqrtf(var + EPSV);
        nsc[tid] = scale;
        nsh[tid] = gb2[tid] - a * m * scale;
    }
    __syncthreads();

    int n0 = blockIdx.x * 128;
    const float4* p4 = (const float4*)g_pre;
    for (int e = tid; e < 128 * 32; e += 128) {
        int r = e >> 5, cc = e & 31;
        int n = n0 + r;
        float4 v = make_float4(0.f, 0.f, 0.f, 0.f);
        if (n < NN) v = p4[n * 32 + cc];
        int c = cc * 4;
        hs[(c + 0) * 129 + r] = gelu_f(v.x * nsc[c + 0] + nsh[c + 0]);
        hs[(c + 1) * 129 + r] = gelu_f(v.y * nsc[c + 1] + nsh[c + 1]);
        hs[(c + 2) * 129 + r] = gelu_f(v.z * nsc[c + 2] + nsh[c + 2]);
        hs[(c + 3) * 129 + r] = gelu_f(v.w * nsc[c + 3] + nsh[c + 3]);
    }
    __syncthreads();

    int n = n0 + tid;
    if (n >= NN) return;

    ull acc1[32];
#pragma unroll
    for (int i = 0; i < 32; i++) acc1[i] = pk2(b1[2 * i], b1[2 * i + 1]);
    for (int k = 0; k < 128; k++) {
        float hv = hs[k * 129 + tid];
        ull a2 = pk2(hv, hv);
        const ull* wr = (const ull*)(W1t + k * 64);
#pragma unroll
        for (int i = 0; i < 32; i++) fma2(acc1[i], a2, wr[i]);
    }
    float y1[64];
#pragma unroll
    for (int i = 0; i < 32; i++) {
        float lo, hi;
        upk2(acc1[i], lo, hi);
        y1[2 * i] = gelu_f(lo);
        y1[2 * i + 1] = gelu_f(hi);
    }
    ull acc2[16];
#pragma unroll
    for (int i = 0; i < 16; i++) acc2[i] = pk2(b2[2 * i], b2[2 * i + 1]);
#pragma unroll 4
    for (int k = 0; k < 64; k++) {
        ull a2 = pk2(y1[k], y1[k]);
        const ull* wr = (const ull*)(W2t + k * 32);
#pragma unroll
        for (int i = 0; i < 16; i++) fma2(acc2[i], a2, wr[i]);
    }
    float s = 0.f;
#pragma unroll
    for (int i = 0; i < 16; i++) {
        float lo, hi;
        upk2(acc2[i], lo, hi);
        s += gelu_f(lo) * w3[2 * i] + gelu_f(hi) * w3[2 * i + 1];
    }
    s += hb3[0];
    out[n] = 1.f / (1.f + expf(-s));
}

// ---------------- launch ----------------
extern "C" void kernel_launch(void* const* d_in, const int* in_sizes, int n_in,
                              void* d_out, int out_size)
{
    const float* x   = (const float*)d_in[0];
    const int*   ei  = (const int*)d_in[1];
    const float* Wl[3] = {(const float*)d_in[2],  (const float*)d_in[8],  (const float*)d_in[14]};
    const float* bl[3] = {(const float*)d_in[3],  (const float*)d_in[9],  (const float*)d_in[15]};
    const float* Wr[3] = {(const float*)d_in[4],  (const float*)d_in[10], (const float*)d_in[16]};
    const float* gw[3] = {(const float*)d_in[5],  (const float*)d_in[11], (const float*)d_in[17]};
    const float* gb[3] = {(const float*)d_in[6],  (const float*)d_in[12], (const float*)d_in[18]};
    const float* ga[3] = {(const float*)d_in[7],  (const float*)d_in[13], (const float*)d_in[19]};
    const float* hW1 = (const float*)d_in[20];
    const float* hb1 = (const float*)d_in[21];
    const float* hW2 = (const float*)d_in[22];
    const float* hb2 = (const float*)d_in[23];
    const float* hW3 = (const float*)d_in[24];
    const float* hb3 = (const float*)d_in[25];
    float* out = (float*)d_out;

    const int SCAN_BLOCKS = (NN + 1023) / 1024;      // 98
    const int MLP_SMEM = (8192 + 2048 + 32 + 64 + 32 + 256 + 128 * 129) * 4;
    cudaFuncSetAttribute(k_mlp, cudaFuncAttributeMaxDynamicSharedMemorySize, MLP_SMEM);
    cudaFuncSetAttribute(k_gemm_mma, cudaFuncAttributeMaxDynamicSharedMemorySize, MMA_SMEM);

    // CSR build
    k_init<<<(NN + 255) / 256, 256>>>();
    k_hist<<<(EE + 255) / 256, 256>>>(ei);
    k_scan1<<<SCAN_BLOCKS, 1024>>>();
    k_scan2<<<1, 128>>>(SCAN_BLOCKS);
    k_scan3<<<(NN + 255) / 256, 256>>>();
    k_fill<<<(EE + 255) / 256, 256>>>(ei);

    // layer 0
    k_agg20<<<(NN * 32 + 255) / 256, 256>>>(x);
    k_gemm0<<<(NN + 63) / 64, 256>>>(x, Wl[0], bl[0], Wr[0]);

    // layers 1, 2: fused-finish tf32 mma gemm -> agg+add+bias+stats
    for (int L = 1; L <= 2; L++) {
        k_gemm_mma<<<148, 256, MMA_SMEM>>>(Wl[L], Wr[L], gw[L - 1], gb[L - 1], ga[L - 1], L - 1);
        k_aggstats<<<782, 256>>>(bl[L], L);
    }

    // MLP head (norm+gelu + finish fused)
    k_mlp<<<(NN + 127) / 128, 128, MLP_SMEM>>>(hW1, hb1, hW2, hb2, hW3, hb3,
                                               gw[2], gb[2], ga[2], out);
}

// round 7
// speedup vs baseline: 1.7546x; 1.0496x over previous
#include <cuda_runtime.h>
#include <cuda_fp16.h>
#include <math.h>

#define NN   100000
#define EE   1600000
#define FIN  20
#define HH   128
#define EPSV 1e-5f
#define NTILES 782            // ceil(NN/128)

// ---------------- scratch ----------------
__device__ __align__(16) unsigned int g_yl16[NN * 64];   // fp16x2: [N][64] half2 = 128 ch
__device__ __align__(16) float g_yr[NN * HH];
__device__ __align__(16) float g_pre[NN * HH];
__device__ __align__(16) float g_a20[NN * FIN];
__device__ int   g_deg[NN];
__device__ int   g_off[NN + 1];
__device__ int   g_csr[EE];
__device__ int   g_bsum[128];
__device__ float g_stats[3][2 * HH];

typedef unsigned long long ull;
typedef unsigned int uint;

__device__ __forceinline__ ull pk2(float lo, float hi) {
    ull r; asm("mov.b64 %0, {%1,%2};" : "=l"(r) : "f"(lo), "f"(hi)); return r;
}
__device__ __forceinline__ void upk2(ull v, float& lo, float& hi) {
    asm("mov.b64 {%0,%1}, %2;" : "=f"(lo), "=f"(hi) : "l"(v));
}
__device__ __forceinline__ void fma2(ull& d, ull a, ull b) {
    asm("fma.rn.f32x2 %0, %1, %2, %0;" : "+l"(d) : "l"(a), "l"(b));
}
__device__ __forceinline__ float gelu_f(float x) {
    return 0.5f * x * (1.0f + erff(x * 0.70710678118654752f));
}
__device__ __forceinline__ uint pack_h2(float lo, float hi) {
    uint r; asm("cvt.rn.f16x2.f32 %0, %2, %1;" : "=r"(r) : "f"(lo), "f"(hi)); return r;
}
__device__ __forceinline__ void mma_f16(float* d, uint a0, uint a1, uint a2, uint a3,
                                        uint b0, uint b1) {
    asm volatile(
        "mma.sync.aligned.m16n8k16.row.col.f32.f16.f16.f32 "
        "{%0,%1,%2,%3}, {%4,%5,%6,%7}, {%8,%9}, {%0,%1,%2,%3};"
        : "+f"(d[0]), "+f"(d[1]), "+f"(d[2]), "+f"(d[3])
        : "r"(a0), "r"(a1), "r"(a2), "r"(a3), "r"(b0), "r"(b1));
}

// ---------------- init + CSR build ----------------
__global__ void k_init() {
    int i = blockIdx.x * blockDim.x + threadIdx.x;
    if (i < NN) g_deg[i] = 0;
    if (i < 3 * 2 * HH) ((float*)g_stats)[i] = 0.f;
}
__global__ void k_hist(const int* __restrict__ ei) {
    int e = blockIdx.x * blockDim.x + threadIdx.x;
    if (e < EE) atomicAdd(&g_deg[ei[EE + e]], 1);
}
__global__ void k_scan1() {
    __shared__ int s[1024];
    int t = threadIdx.x;
    int i = blockIdx.x * 1024 + t;
    int v = (i < NN) ? g_deg[i] : 0;
    s[t] = v;
    __syncthreads();
#pragma unroll
    for (int d = 1; d < 1024; d <<= 1) {
        int x = (t >= d) ? s[t - d] : 0;
        __syncthreads();
        s[t] += x;
        __syncthreads();
    }
    if (i < NN) g_off[i + 1] = s[t];
    if (t == 1023) g_bsum[blockIdx.x] = s[1023];
}
__global__ void k_scan2(int nb) {
    __shared__ int s[128];
    int t = threadIdx.x;
    int v = (t < nb) ? g_bsum[t] : 0;
    s[t] = v;
    __syncthreads();
#pragma unroll
    for (int d = 1; d < 128; d <<= 1) {
        int x = (t >= d) ? s[t - d] : 0;
        __syncthreads();
        s[t] += x;
        __syncthreads();
    }
    if (t < nb) g_bsum[t] = s[t] - v;
}
__global__ void k_scan3() {
    int i = blockIdx.x * blockDim.x + threadIdx.x;
    if (i < NN) {
        int tot = g_off[i + 1] + g_bsum[i >> 10];
        g_off[i + 1] = tot;
        int d = g_deg[i];
        g_deg[i] = tot - d;
        if (i == 0) g_off[0] = 0;
    }
}
__global__ void k_fill(const int* __restrict__ ei) {
    int e = blockIdx.x * blockDim.x + threadIdx.x;
    if (e < EE) {
        int d = ei[EE + e];
        int pos = atomicAdd(&g_deg[d], 1);
        g_csr[pos] = ei[e];
    }
}

// ---------------- layer-0 aggregation (20 cols) ----------------
__global__ void k_agg20(const float* __restrict__ x) {
    int w = (blockIdx.x * blockDim.x + threadIdx.x) >> 5;
    int lane = threadIdx.x & 31;
    if (w >= NN) return;
    int off = g_off[w], end = g_off[w + 1];
    float acc = 0.f;
    for (int j = off; j < end; j += 32) {
        int idx = (j + lane < end) ? g_csr[j + lane] : 0;
        int cnt = min(32, end - j);
        int t = 0;
        for (; t + 4 <= cnt; t += 4) {
            int s0 = __shfl_sync(0xffffffffu, idx, t);
            int s1 = __shfl_sync(0xffffffffu, idx, t + 1);
            int s2 = __shfl_sync(0xffffffffu, idx, t + 2);
            int s3 = __shfl_sync(0xffffffffu, idx, t + 3);
            if (lane < FIN) {
                float v0 = x[s0 * FIN + lane], v1 = x[s1 * FIN + lane];
                float v2 = x[s2 * FIN + lane], v3 = x[s3 * FIN + lane];
                acc += (v0 + v1) + (v2 + v3);
            }
        }
        for (; t < cnt; t++) {
            int s = __shfl_sync(0xffffffffu, idx, t);
            if (lane < FIN) acc += x[s * FIN + lane];
        }
    }
    if (lane < FIN) {
        int deg = end - off;
        g_a20[w * FIN + lane] = acc * (deg > 0 ? 1.f / (float)deg : 0.f);
    }
}

// ---------------- layer-0 GEMM (K=20) + bias + stats ----------------
__global__ __launch_bounds__(256) void k_gemm0(
    const float* __restrict__ x, const float* __restrict__ Wl,
    const float* __restrict__ bl, const float* __restrict__ Wr)
{
    __shared__ float Wls[FIN][HH], Wrs[FIN][HH], bls[HH];
    __shared__ float As[64][FIN + 1], Xs[64][FIN + 1];
    __shared__ float red[16][HH];
    int tid = threadIdx.x;
    for (int e = tid; e < HH * FIN; e += 256) {
        int o = e / FIN, k = e % FIN;
        Wls[k][o] = Wl[e];
        Wrs[k][o] = Wr[e];
    }
    if (tid < HH) bls[tid] = bl[tid];
    int n0 = blockIdx.x * 64;
    for (int e = tid; e < 64 * FIN; e += 256) {
        int i = e / FIN, k = e % FIN;
        int n = n0 + i;
        As[i][k] = (n < NN) ? g_a20[n * FIN + k] : 0.f;
        Xs[i][k] = (n < NN) ? x[n * FIN + k] : 0.f;
    }
    __syncthreads();
    int tm = tid >> 4, tn = tid & 15;
    ull acc[4][4];
#pragma unroll
    for (int r = 0; r < 4; r++)
#pragma unroll
        for (int c = 0; c < 4; c++)
            acc[r][c] = pk2(bls[tn * 8 + 2 * c], bls[tn * 8 + 2 * c + 1]);
#pragma unroll 4
    for (int k = 0; k < FIN; k++) {
        const ull* wl = (const ull*)&Wls[k][tn * 8];
        const ull* wr = (const ull*)&Wrs[k][tn * 8];
#pragma unroll
        for (int r = 0; r < 4; r++) {
            ull a2 = pk2(As[tm * 4 + r][k], As[tm * 4 + r][k]);
            ull x2 = pk2(Xs[tm * 4 + r][k], Xs[tm * 4 + r][k]);
#pragma unroll
            for (int c = 0; c < 4; c++) { fma2(acc[r][c], a2, wl[c]); fma2(acc[r][c], x2, wr[c]); }
        }
    }
    float av[4][8];
    float s[8] = {0,0,0,0,0,0,0,0}, s2[8] = {0,0,0,0,0,0,0,0};
#pragma unroll
    for (int r = 0; r < 4; r++) {
#pragma unroll
        for (int c = 0; c < 4; c++) upk2(acc[r][c], av[r][2 * c], av[r][2 * c + 1]);
        int n = n0 + tm * 4 + r;
        if (n < NN) {
            float4* o4 = (float4*)(g_pre + n * HH + tn * 8);
            o4[0] = make_float4(av[r][0], av[r][1], av[r][2], av[r][3]);
            o4[1] = make_float4(av[r][4], av[r][5], av[r][6], av[r][7]);
#pragma unroll
            for (int j = 0; j < 8; j++) { s[j] += av[r][j]; s2[j] += av[r][j] * av[r][j]; }
        }
    }
#pragma unroll
    for (int j = 0; j < 8; j++) red[tm][tn * 8 + j] = s[j];
    __syncthreads();
    if (tid < HH) {
        float t = 0.f;
#pragma unroll
        for (int w = 0; w < 16; w++) t += red[w][tid];
        atomicAdd(&g_stats[0][tid], t);
    }
    __syncthreads();
#pragma unroll
    for (int j = 0; j < 8; j++) red[tm][tn * 8 + j] = s2[j];
    __syncthreads();
    if (tid < HH) {
        float t = 0.f;
#pragma unroll
        for (int w = 0; w < 16; w++) t += red[w][tid];
        atomicAdd(&g_stats[0][HH + tid], t);
    }
}

// ---------------- FP16 mma.sync dual GEMM (fragment-order smem layouts) ----------------
// m16n8k16: A frag 4 regs (two k8 halves x two row halves, half2 k=2tr,2tr+1)
// Bf: [cg(2)][k16(8)][jp(8)][lane(32) x uint4 = (j0b0,j0b1,j1b0,j1b1)]  64KB
// Af: [rt(8)][k16(8)] rows of 132 uints, lane uint4 = (a0,a1,a2,a3)    33.8KB
#define BF_UINTS (2 * 8 * 8 * 128)
#define AF_UINTS (8 * 8 * 132)
#define OFF_BF   0
#define OFF_AF   (BF_UINTS * 4)
#define OFF_NSC  (OFF_AF + AF_UINTS * 4)
#define OFF_NSH  (OFF_NSC + 512)
#define MMA_SMEM (OFF_NSH + 512)

__global__ __launch_bounds__(256, 1) void k_gemm_mma(
    const float* __restrict__ Wl, const float* __restrict__ Wr,
    const float* __restrict__ gw, const float* __restrict__ gb,
    const float* __restrict__ ga, int Lm1)
{
    extern __shared__ char sm[];
    uint*  Bf  = (uint*)(sm + OFF_BF);
    uint*  Af  = (uint*)(sm + OFF_AF);
    float* nsc = (float*)(sm + OFF_NSC);
    float* nsh = (float*)(sm + OFF_NSH);
    int tid = threadIdx.x;
    int wid = tid >> 5, lane = tid & 31;
    int tq = lane >> 2, tr = lane & 3;
    int rg = wid & 3, cg = wid >> 2;

    // fused GraphNorm finish
    if (tid < HH) {
        float invn = 1.f / (float)NN;
        float m  = g_stats[Lm1][tid] * invn;
        float e2 = g_stats[Lm1][HH + tid] * invn;
        float a = ga[tid];
        float var = fmaxf(e2 - m * m * (2.f * a - a * a), 0.f);
        float scale = gw[tid] * rsqrtf(var + EPSV);
        nsc[tid] = scale;
        nsh[tid] = gb[tid] - a * m * scale;
    }

    // stage B fragments once: out-cols 0..127 = Wl rows, 128..255 = Wr rows
    for (int e = tid; e < 256 * 32; e += 256) {
        int c = e >> 5, c4 = e & 31;
        const float4* src = (const float4*)((c < 128) ? Wl : Wr);
        float4 v = src[(c & 127) * 32 + c4];
        uint h0 = pack_h2(v.x, v.y);     // k = 4c4, 4c4+1   -> p = 2c4
        uint h1 = pack_h2(v.z, v.w);     // p = 2c4+1
        int cgi = c >> 7, cl = c & 127;
        int j = cl >> 3, jp = j >> 1, jl = j & 1, nq = cl & 7;
        int p = 2 * c4;
        int k16 = p >> 3, q = p & 7;
        int reg = (q >= 4) ? 1 : 0;
        uint* dst = Bf + (((cgi * 8 + k16) * 8 + jp) << 7) + jl * 2 + reg;
        dst[(nq * 4 + (q & 3)) * 4]       = h0;
        dst[(nq * 4 + ((q + 1) & 3)) * 4] = h1;
    }

    const float4* P4 = (const float4*)g_pre;

    for (int tile = blockIdx.x; tile < NTILES; tile += gridDim.x) {
        int m0 = tile * 128;
        __syncthreads();   // prior tile's fragment reads done
        // stage A tile in fragment order (norm + gelu + fp16 fused)
        for (int e = tid; e < 128 * 32; e += 256) {
            int r = e >> 5, c4 = e & 31;
            int row = m0 + r;
            float4 v = make_float4(0.f, 0.f, 0.f, 0.f);
            if (row < NN) v = P4[row * 32 + c4];
            int c = c4 * 4;
            float g0 = gelu_f(v.x * nsc[c + 0] + nsh[c + 0]);
            float g1 = gelu_f(v.y * nsc[c + 1] + nsh[c + 1]);
            float g2 = gelu_f(v.z * nsc[c + 2] + nsh[c + 2]);
            float g3 = gelu_f(v.w * nsc[c + 3] + nsh[c + 3]);
            uint h0 = pack_h2(g0, g1);   // p = 2c4
            uint h1 = pack_h2(g2, g3);   // p = 2c4+1
            int rt = r >> 4, rr = r & 15, rh = rr >> 3, tq_ = rr & 7;
            int p = 2 * c4;
            int k16 = p >> 3, q = p & 7;
            int reg = ((q >= 4) ? 2 : 0) + rh;
            uint* dst = Af + (rt * 8 + k16) * 132 + reg;
            dst[(tq_ * 4 + (q & 3)) * 4]       = h0;
            dst[(tq_ * 4 + ((q + 1) & 3)) * 4] = h1;
        }
        __syncthreads();

        int rt0 = rg * 2, rt1 = rg * 2 + 1;
        float acc[2][16][4];
#pragma unroll
        for (int t2 = 0; t2 < 2; t2++)
#pragma unroll
            for (int j = 0; j < 16; j++)
#pragma unroll
                for (int c = 0; c < 4; c++) acc[t2][j][c] = 0.f;

#pragma unroll
        for (int k16 = 0; k16 < 8; k16++) {
            uint4 A0 = ((const uint4*)(Af + (rt0 * 8 + k16) * 132))[lane];
            uint4 A1 = ((const uint4*)(Af + (rt1 * 8 + k16) * 132))[lane];
            const uint4* Bp = (const uint4*)(Bf + (((cg * 8 + k16) * 8) << 7));
#pragma unroll
            for (int jp = 0; jp < 8; jp++) {
                uint4 B = Bp[(jp << 5) + lane];
                mma_f16(acc[0][jp * 2],     A0.x, A0.y, A0.z, A0.w, B.x, B.y);
                mma_f16(acc[1][jp * 2],     A1.x, A1.y, A1.z, A1.w, B.x, B.y);
                mma_f16(acc[0][jp * 2 + 1], A0.x, A0.y, A0.z, A0.w, B.z, B.w);
                mma_f16(acc[1][jp * 2 + 1], A1.x, A1.y, A1.z, A1.w, B.z, B.w);
            }
        }

        // epilogue: warp covers rows rg*32..+32, cols cg*128..+128
#pragma unroll
        for (int t2 = 0; t2 < 2; t2++) {
            int row0 = m0 + rg * 32 + t2 * 16 + tq;
            if (cg == 0) {
#pragma unroll
                for (int j = 0; j < 16; j++) {
                    int hidx = j * 4 + tr;     // half2 index (cols j*8+tr*2, +1)
                    if (row0 < NN)
                        g_yl16[row0 * 64 + hidx] = pack_h2(acc[t2][j][0], acc[t2][j][1]);
                    if (row0 + 8 < NN)
                        g_yl16[(row0 + 8) * 64 + hidx] = pack_h2(acc[t2][j][2], acc[t2][j][3]);
                }
            } else {
#pragma unroll
                for (int j = 0; j < 16; j++) {
                    int col = j * 8 + tr * 2;
                    if (row0 < NN)
                        *(float2*)(g_yr + row0 * HH + col) = make_float2(acc[t2][j][0], acc[t2][j][1]);
                    if (row0 + 8 < NN)
                        *(float2*)(g_yr + (row0 + 8) * HH + col) = make_float2(acc[t2][j][2], acc[t2][j][3]);
                }
            }
        }
    }
}

// ---------------- aggregation of yl(fp16) + add yr + bias + stats ----------------
__global__ __launch_bounds__(256) void k_aggstats(const float* __restrict__ bl, int L)
{
    __shared__ float red[8][HH];
    int tid = threadIdx.x;
    int lane = tid & 31, wp = tid >> 5;
    const uint2* yl2 = (const uint2*)g_yl16;
    const float4* yr4 = (const float4*)g_yr;
    float4 bias = ((const float4*)bl)[lane];
    float s[4] = {0, 0, 0, 0}, s2[4] = {0, 0, 0, 0};
    int gw = blockIdx.x * 8 + wp;
    const int stride = gridDim.x * 8;
    for (int w = gw; w < NN; w += stride) {
        int off = g_off[w], end = g_off[w + 1];
        float4 acc = make_float4(0.f, 0.f, 0.f, 0.f);
        for (int j = off; j < end; j += 32) {
            int idx = (j + lane < end) ? g_csr[j + lane] : 0;
            int cnt = min(32, end - j);
            int t = 0;
            for (; t + 4 <= cnt; t += 4) {
                int s0 = __shfl_sync(0xffffffffu, idx, t);
                int s1 = __shfl_sync(0xffffffffu, idx, t + 1);
                int s2i = __shfl_sync(0xffffffffu, idx, t + 2);
                int s3 = __shfl_sync(0xffffffffu, idx, t + 3);
                uint2 u0 = yl2[s0 * 32 + lane];
                uint2 u1 = yl2[s1 * 32 + lane];
                uint2 u2 = yl2[s2i * 32 + lane];
                uint2 u3 = yl2[s3 * 32 + lane];
                float2 a0 = __half22float2(*(const __half2*)&u0.x);
                float2 b0 = __half22float2(*(const __half2*)&u0.y);
                float2 a1 = __half22float2(*(const __half2*)&u1.x);
                float2 b1 = __half22float2(*(const __half2*)&u1.y);
                float2 a2 = __half22float2(*(const __half2*)&u2.x);
                float2 b2 = __half22float2(*(const __half2*)&u2.y);
                float2 a3 = __half22float2(*(const __half2*)&u3.x);
                float2 b3 = __half22float2(*(const __half2*)&u3.y);
                acc.x += (a0.x + a1.x) + (a2.x + a3.x);
                acc.y += (a0.y + a1.y) + (a2.y + a3.y);
                acc.z += (b0.x + b1.x) + (b2.x + b3.x);
                acc.w += (b0.y + b1.y) + (b2.y + b3.y);
            }
            for (; t < cnt; t++) {
                int sx = __shfl_sync(0xffffffffu, idx, t);
                uint2 u = yl2[sx * 32 + lane];
                float2 a = __half22float2(*(const __half2*)&u.x);
                float2 b = __half22float2(*(const __half2*)&u.y);
                acc.x += a.x; acc.y += a.y; acc.z += b.x; acc.w += b.y;
            }
        }
        int deg = end - off;
        float inv = (deg > 0) ? 1.f / (float)deg : 0.f;
        float4 r = yr4[w * 32 + lane];
        r.x = acc.x * inv + r.x + bias.x;
        r.y = acc.y * inv + r.y + bias.y;
        r.z = acc.z * inv + r.z + bias.z;
        r.w = acc.w * inv + r.w + bias.w;
        ((float4*)g_pre)[w * 32 + lane] = r;
        s[0] += r.x; s2[0] += r.x * r.x;
        s[1] += r.y; s2[1] += r.y * r.y;
        s[2] += r.z; s2[2] += r.z * r.z;
        s[3] += r.w; s2[3] += r.w * r.w;
    }
#pragma unroll
    for (int i = 0; i < 4; i++) red[wp][lane * 4 + i] = s[i];
    __syncthreads();
    if (tid < HH) {
        float t = 0.f;
#pragma unroll
        for (int w = 0; w < 8; w++) t += red[w][tid];
        atomicAdd(&g_stats[L][tid], t);
    }
    __syncthreads();
#pragma unroll
    for (int i = 0; i < 4; i++) red[wp][lane * 4 + i] = s2[i];
    __syncthreads();
    if (tid < HH) {
        float t = 0.f;
#pragma unroll
        for (int w = 0; w < 8; w++) t += red[w][tid];
        atomicAdd(&g_stats[L][HH + tid], t);
    }
}

// ---------------- fused MLP head with norm+gelu on input (finish fused) ----------------
__global__ __launch_bounds__(128) void k_mlp(
    const float* __restrict__ hW1, const float* __restrict__ hb1,
    const float* __restrict__ hW2, const float* __restrict__ hb2,
    const float* __restrict__ hW3, const float* __restrict__ hb3,
    const float* __restrict__ gw2, const float* __restrict__ gb2,
    const float* __restrict__ ga2,
    float* __restrict__ out)
{
    extern __shared__ float smf[];
    float* W1t = smf;                // [128][64]
    float* W2t = W1t + 128 * 64;     // [64][32]
    float* w3  = W2t + 64 * 32;      // [32]
    float* b1  = w3 + 32;            // [64]
    float* b2  = b1 + 64;            // [32]
    float* nsc = b2 + 32;            // [128]
    float* nsh = nsc + 128;          // [128]
    float* hs  = nsh + 128;          // [128][129]

    int tid = threadIdx.x;
    for (int e = tid; e < 8192; e += 128) { int o = e >> 7, k = e & 127; W1t[k * 64 + o] = hW1[e]; }
    for (int e = tid; e < 2048; e += 128) { int o = e >> 6, k = e & 63;  W2t[k * 32 + o] = hW2[e]; }
    if (tid < 32) w3[tid] = hW3[tid];
    if (tid < 64) b1[tid] = hb1[tid];
    if (tid < 32) b2[tid] = hb2[tid];
    {
        float invn = 1.f / (float)NN;
        float m  = g_stats[2][tid] * invn;
        float e2 = g_stats[2][HH + tid] * invn;
        float a = ga2[tid];
        float var = fmaxf(e2 - m * m * (2.f * a - a * a), 0.f);
        float scale = gw2[tid] * rsqrtf(var + EPSV);
        nsc[tid] = scale;
        nsh[tid] = gb2[tid] - a * m * scale;
    }
    __syncthreads();

    int n0 = blockIdx.x * 128;
    const float4* p4 = (const float4*)g_pre;
    for (int e = tid; e < 128 * 32; e += 128) {
        int r = e >> 5, cc = e & 31;
        int n = n0 + r;
        float4 v = make_float4(0.f, 0.f, 0.f, 0.f);
        if (n < NN) v = p4[n * 32 + cc];
        int c = cc * 4;
        hs[(c + 0) * 129 + r] = gelu_f(v.x * nsc[c + 0] + nsh[c + 0]);
        hs[(c + 1) * 129 + r] = gelu_f(v.y * nsc[c + 1] + nsh[c + 1]);
        hs[(c + 2) * 129 + r] = gelu_f(v.z * nsc[c + 2] + nsh[c + 2]);
        hs[(c + 3) * 129 + r] = gelu_f(v.w * nsc[c + 3] + nsh[c + 3]);
    }
    __syncthreads();

    int n = n0 + tid;
    if (n >= NN) return;

    ull acc1[32];
#pragma unroll
    for (int i = 0; i < 32; i++) acc1[i] = pk2(b1[2 * i], b1[2 * i + 1]);
    for (int k = 0; k < 128; k++) {
        float hv = hs[k * 129 + tid];
        ull a2 = pk2(hv, hv);
        const ull* wr = (const ull*)(W1t + k * 64);
#pragma unroll
        for (int i = 0; i < 32; i++) fma2(acc1[i], a2, wr[i]);
    }
    float y1[64];
#pragma unroll
    for (int i = 0; i < 32; i++) {
        float lo, hi;
        upk2(acc1[i], lo, hi);
        y1[2 * i] = gelu_f(lo);
        y1[2 * i + 1] = gelu_f(hi);
    }
    ull acc2[16];
#pragma unroll
    for (int i = 0; i < 16; i++) acc2[i] = pk2(b2[2 * i], b2[2 * i + 1]);
#pragma unroll 4
    for (int k = 0; k < 64; k++) {
        ull a2 = pk2(y1[k], y1[k]);
        const ull* wr = (const ull*)(W2t + k * 32);
#pragma unroll
        for (int i = 0; i < 16; i++) fma2(acc2[i], a2, wr[i]);
    }
    float s = 0.f;
#pragma unroll
    for (int i = 0; i < 16; i++) {
        float lo, hi;
        upk2(acc2[i], lo, hi);
        s += gelu_f(lo) * w3[2 * i] + gelu_f(hi) * w3[2 * i + 1];
    }
    s += hb3[0];
    out[n] = 1.f / (1.f + expf(-s));
}

// ---------------- launch ----------------
extern "C" void kernel_launch(void* const* d_in, const int* in_sizes, int n_in,
                              void* d_out, int out_size)
{
    const float* x   = (const float*)d_in[0];
    const int*   ei  = (const int*)d_in[1];
    const float* Wl[3] = {(const float*)d_in[2],  (const float*)d_in[8],  (const float*)d_in[14]};
    const float* bl[3] = {(const float*)d_in[3],  (const float*)d_in[9],  (const float*)d_in[15]};
    const float* Wr[3] = {(const float*)d_in[4],  (const float*)d_in[10], (const float*)d_in[16]};
    const float* gw[3] = {(const float*)d_in[5],  (const float*)d_in[11], (const float*)d_in[17]};
    const float* gb[3] = {(const float*)d_in[6],  (const float*)d_in[12], (const float*)d_in[18]};
    const float* ga[3] = {(const float*)d_in[7],  (const float*)d_in[13], (const float*)d_in[19]};
    const float* hW1 = (const float*)d_in[20];
    const float* hb1 = (const float*)d_in[21];
    const float* hW2 = (const float*)d_in[22];
    const float* hb2 = (const float*)d_in[23];
    const float* hW3 = (const float*)d_in[24];
    const float* hb3 = (const float*)d_in[25];
    float* out = (float*)d_out;

    const int SCAN_BLOCKS = (NN + 1023) / 1024;      // 98
    const int MLP_SMEM = (8192 + 2048 + 32 + 64 + 32 + 256 + 128 * 129) * 4;
    cudaFuncSetAttribute(k_mlp, cudaFuncAttributeMaxDynamicSharedMemorySize, MLP_SMEM);
    cudaFuncSetAttribute(k_gemm_mma, cudaFuncAttributeMaxDynamicSharedMemorySize, MMA_SMEM);

    // CSR build
    k_init<<<(NN + 255) / 256, 256>>>();
    k_hist<<<(EE + 255) / 256, 256>>>(ei);
    k_scan1<<<SCAN_BLOCKS, 1024>>>();
    k_scan2<<<1, 128>>>(SCAN_BLOCKS);
    k_scan3<<<(NN + 255) / 256, 256>>>();
    k_fill<<<(EE + 255) / 256, 256>>>(ei);

    // layer 0
    k_agg20<<<(NN * 32 + 255) / 256, 256>>>(x);
    k_gemm0<<<(NN + 63) / 64, 256>>>(x, Wl[0], bl[0], Wr[0]);

    // layers 1, 2: fused-finish fp16 mma gemm -> agg+add+bias+stats
    for (int L = 1; L <= 2; L++) {
        k_gemm_mma<<<148, 256, MMA_SMEM>>>(Wl[L], Wr[L], gw[L - 1], gb[L - 1], ga[L - 1], L - 1);
        k_aggstats<<<782, 256>>>(bl[L], L);
    }

    // MLP head (norm+gelu + finish fused)
    k_mlp<<<(NN + 127) / 128, 128, MLP_SMEM>>>(hW1, hb1, hW2, hb2, hW3, hb3,
                                               gw[2], gb[2], ga[2], out);
}